// round 12
// baseline (speedup 1.0000x reference)
#include <cuda_runtime.h>
#include <cuda_bf16.h>
#include <math.h>
#include <stdint.h>

#define D_MODEL 1024
#define NUM_HEADS 16
#define DK 64
#define HALF 32
#define BB 4
#define SS 2048
#define MM (BB * SS)           // 8192 tokens
#define LOG2_THETA 13.287712379549449f   // log2(10000)

// ---------------- scratch (device globals: no allocation allowed) ----------
__device__ float g_v[(size_t)MM * D_MODEL];            // V projection (fp32)

__device__ __nv_bfloat16 g_xh[(size_t)MM * D_MODEL];
__device__ __nv_bfloat16 g_xl[(size_t)MM * D_MODEL];
__device__ __nv_bfloat16 g_ah[(size_t)MM * D_MODEL];   // attention out hi
__device__ __nv_bfloat16 g_al[(size_t)MM * D_MODEL];   // attention out lo
__device__ __nv_bfloat16 g_wh[4][(size_t)D_MODEL * D_MODEL];
__device__ __nv_bfloat16 g_wl[4][(size_t)D_MODEL * D_MODEL];

__device__ __nv_bfloat16 g_qh[(size_t)MM * D_MODEL];
__device__ __nv_bfloat16 g_ql[(size_t)MM * D_MODEL];
__device__ __nv_bfloat16 g_kh[(size_t)MM * D_MODEL];
__device__ __nv_bfloat16 g_kl[(size_t)MM * D_MODEL];
__device__ __nv_bfloat16 g_vth[(size_t)MM * D_MODEL];  // [(b*16+h)*64+d][S]
__device__ __nv_bfloat16 g_vtl[(size_t)MM * D_MODEL];

__device__ float2 g_rope[(size_t)SS * HALF];           // {cos, sin} table

// ---------------------------------------------------------------------------
__device__ __forceinline__ uint32_t smem_u32(const void* p) {
    return (uint32_t)__cvta_generic_to_shared(p);
}
#define CP_ASYNC16(dst, src) \
    asm volatile("cp.async.cg.shared.global [%0], [%1], 16;\n" :: "r"(dst), "l"(src))
#define CP_COMMIT() asm volatile("cp.async.commit_group;\n" ::: "memory")
#define CP_WAIT0()  asm volatile("cp.async.wait_group 0;\n" ::: "memory")
// .noinc is load-bearing: default form pre-increments the pending count and
// the async arrive only cancels it (net zero) -> barrier never flips.
#define CP_MBAR_ARRIVE(addr) \
    asm volatile("cp.async.mbarrier.arrive.noinc.shared.b64 [%0];" :: "r"(addr) : "memory")
#define MBAR_INIT(addr, cnt) \
    asm volatile("mbarrier.init.shared.b64 [%0], %1;" \
                 :: "r"((uint32_t)(addr)), "r"((uint32_t)(cnt)) : "memory")
#define MBAR_WAIT(addr, ph) \
    asm volatile("{\n\t.reg .pred P1;\n\tWL_%=:\n\t" \
                 "mbarrier.try_wait.parity.acquire.cta.shared::cta.b64 P1, [%0], %1;\n\t" \
                 "@!P1 bra WL_%=;\n\t}" :: "r"((uint32_t)(addr)), "r"((uint32_t)(ph)) : "memory")
#define BAR_ARRIVE(id) \
    asm volatile("bar.arrive %0, %1;" :: "r"(id), "r"(512) : "memory")
#define BAR_SYNC(id) \
    asm volatile("bar.sync %0, %1;" :: "r"(id), "r"(512) : "memory")

__device__ __forceinline__ void mma_bf16(float c[4], const uint32_t a[4],
                                         const uint32_t b[2]) {
    asm volatile(
        "mma.sync.aligned.m16n8k16.row.col.f32.bf16.bf16.f32 "
        "{%0,%1,%2,%3}, {%4,%5,%6,%7}, {%8,%9}, {%0,%1,%2,%3};\n"
        : "+f"(c[0]), "+f"(c[1]), "+f"(c[2]), "+f"(c[3])
        : "r"(a[0]), "r"(a[1]), "r"(a[2]), "r"(a[3]), "r"(b[0]), "r"(b[1]));
}

__device__ __forceinline__ void split2(float x, float y, uint32_t& hi, uint32_t& lo) {
    __nv_bfloat162 h = __floats2bfloat162_rn(x, y);
    float hx = __bfloat162float(h.x), hy = __bfloat162float(h.y);
    __nv_bfloat162 l = __floats2bfloat162_rn(x - hx, y - hy);
    hi = *(uint32_t*)&h;
    lo = *(uint32_t*)&l;
}

// ---------------------------------------------------------------------------
// RoPE cos/sin table
// ---------------------------------------------------------------------------
__global__ void __launch_bounds__(256) rope_table_kernel(
    const int* __restrict__ pos, float2* __restrict__ tab)
{
    int idx = blockIdx.x * blockDim.x + threadIdx.x;   // < SS*HALF
    int s = idx >> 5, i = idx & (HALF - 1);
    float p = (float)pos[s];
    float inv_freq = exp2f(-(float)i * (LOG2_THETA / (float)HALF));
    float sn, cs;
    sincosf(p * inv_freq, &sn, &cs);
    tab[idx] = make_float2(cs, sn);
}

// ---------------------------------------------------------------------------
// fp32 -> (bf16 hi, bf16 lo) splits
// ---------------------------------------------------------------------------
__global__ void __launch_bounds__(256) split_bf16_kernel(
    const float* __restrict__ src, __nv_bfloat16* __restrict__ hi,
    __nv_bfloat16* __restrict__ lo, int n4)
{
    int i = blockIdx.x * blockDim.x + threadIdx.x;
    if (i >= n4) return;
    float4 v = ((const float4*)src)[i];
    uint32_t h0, l0, h1, l1;
    split2(v.x, v.y, h0, l0);
    split2(v.z, v.w, h1, l1);
    ((uint32_t*)hi)[i * 2 + 0] = h0;
    ((uint32_t*)hi)[i * 2 + 1] = h1;
    ((uint32_t*)lo)[i * 2 + 0] = l0;
    ((uint32_t*)lo)[i * 2 + 1] = l1;
}

__global__ void __launch_bounds__(256) split4_bf16_kernel(
    const float* __restrict__ w0, const float* __restrict__ w1,
    const float* __restrict__ w2, const float* __restrict__ w3,
    __nv_bfloat16* __restrict__ hiB, __nv_bfloat16* __restrict__ loB, int n4)
{
    int i = blockIdx.x * blockDim.x + threadIdx.x;
    if (i >= n4) return;
    const int zz = blockIdx.y;
    const float* src = (zz == 0) ? w0 : (zz == 1) ? w1 : (zz == 2) ? w2 : w3;
    __nv_bfloat16* hi = hiB + (size_t)zz * D_MODEL * D_MODEL;
    __nv_bfloat16* lo = loB + (size_t)zz * D_MODEL * D_MODEL;
    float4 v = ((const float4*)src)[i];
    uint32_t h0, l0, h1, l1;
    split2(v.x, v.y, h0, l0);
    split2(v.z, v.w, h1, l1);
    ((uint32_t*)hi)[i * 2 + 0] = h0;
    ((uint32_t*)hi)[i * 2 + 1] = h1;
    ((uint32_t*)lo)[i * 2 + 0] = l0;
    ((uint32_t*)lo)[i * 2 + 1] = l1;
}

// ---------------------------------------------------------------------------
// bf16x3 mma.sync GEMM (NT), 4-stage DECOUPLED pipeline:
//  - per-stage mbarrier (cp.async.mbarrier.arrive.noinc, count=256) = data-ready
//  - per-ring-slot named barrier (arrive@read-done, sync@before-write, 512)
//  No __syncthreads in the mainloop: warps free-run with ~1 iter of slack.
// ---------------------------------------------------------------------------
__device__ __forceinline__ void load_stage4(
    const __nv_bfloat16* __restrict__ gAh, const __nv_bfloat16* __restrict__ gAl,
    const __nv_bfloat16* __restrict__ gBh, const __nv_bfloat16* __restrict__ gBl,
    int Kdim, int k0, uint32_t* sb, int tid)
{
    const int m = tid >> 1;
    const int q = tid & 1;
    const size_t src = (size_t)m * Kdim + k0 + q * 8;
    const int aw = ((((m >> 4) * 4 + ((m >> 3) & 1) + 2 * q)) << 5) + (m & 7) * 4;
    const int bw = ((((m >> 3) * 2 + q)) << 5) + (m & 7) * 4;
    CP_ASYNC16(smem_u32(sb + aw),        gAh + src);
    CP_ASYNC16(smem_u32(sb + 1024 + aw), gAl + src);
    CP_ASYNC16(smem_u32(sb + 2048 + bw), gBh + src);
    CP_ASYNC16(smem_u32(sb + 3072 + bw), gBl + src);
}

template <int FUSED>
__global__ void __launch_bounds__(256) gemm_bf16x3_nt(
    const __nv_bfloat16* __restrict__ Ah, const __nv_bfloat16* __restrict__ Al,
    const __nv_bfloat16* __restrict__ WhB, const __nv_bfloat16* __restrict__ WlB,
    float* __restrict__ Cf,
    __nv_bfloat16* __restrict__ qh, __nv_bfloat16* __restrict__ ql,
    __nv_bfloat16* __restrict__ kh, __nv_bfloat16* __restrict__ kl,
    const float2* __restrict__ rope,
    int Mdim, int Ndim, int Kdim)
{
    extern __shared__ uint32_t smem4[];   // 4 stages x 4096 u32 = 64KB
    __shared__ uint64_t fullb[4];         // per-stage data-ready mbarriers

    const int tid  = threadIdx.x;
    const int lane = tid & 31;
    const int warp = tid >> 5;
    const int wy   = warp >> 2;
    const int wx   = warp & 3;
    const int row0 = blockIdx.y * 128;
    const int col0 = blockIdx.x * 128;
    const int z    = blockIdx.z;
    const size_t zw = (size_t)z * D_MODEL * D_MODEL;
    const uint32_t fb = smem_u32(fullb);

    const __nv_bfloat16* gAh = Ah + (size_t)row0 * Kdim;
    const __nv_bfloat16* gAl = Al + (size_t)row0 * Kdim;
    const __nv_bfloat16* gBh = WhB + zw + (size_t)col0 * Kdim;
    const __nv_bfloat16* gBl = WlB + zw + (size_t)col0 * Kdim;

    if (tid == 0) {
#pragma unroll
        for (int s = 0; s < 4; ++s) MBAR_INIT(fb + 8 * s, 256);
    }
    __syncthreads();

    float c[4][4][4];
#pragma unroll
    for (int i = 0; i < 4; ++i)
#pragma unroll
        for (int j = 0; j < 4; ++j)
#pragma unroll
            for (int r = 0; r < 4; ++r) c[i][j][r] = 0.f;

    const int NT = Kdim / 16;             // 64 (multiple of 4)
    // prologue: stages 0..2
#pragma unroll
    for (int s = 0; s < 3; ++s) {
        load_stage4(gAh, gAl, gBh, gBl, Kdim, s * 16, smem4 + s * 4096, tid);
        CP_MBAR_ARRIVE(fb + 8 * s);
    }
    BAR_ARRIVE(4);   // pre-arm WAR barrier for ring slot 3 (first write at t=0)

    int phs[4] = {0, 0, 0, 0};

    for (int tt = 0; tt < NT; tt += 4) {
#pragma unroll
        for (int u = 0; u < 4; ++u) {
            const int t = tt + u;
            MBAR_WAIT(fb + 8 * u, phs[u]);
            phs[u] ^= 1;

            const uint32_t* sb  = smem4 + u * 4096;
            const uint32_t* pAh = sb;
            const uint32_t* pAl = sb + 1024;
            const uint32_t* pBh = sb + 2048;
            const uint32_t* pBl = sb + 3072;

            uint32_t ah[4][4], al[4][4], bh[4][2], bl[4][2];
#pragma unroll
            for (int i = 0; i < 4; ++i) {
                const int base = (((wy * 4 + i) * 4) << 5) + lane;
#pragma unroll
                for (int r = 0; r < 4; ++r) {
                    ah[i][r] = pAh[base + (r << 5)];
                    al[i][r] = pAl[base + (r << 5)];
                }
            }
#pragma unroll
            for (int j = 0; j < 4; ++j) {
                const int base = (((wx * 4 + j) * 2) << 5) + lane;
#pragma unroll
                for (int r = 0; r < 2; ++r) {
                    bh[j][r] = pBh[base + (r << 5)];
                    bl[j][r] = pBl[base + (r << 5)];
                }
            }

            if (t + 3 < NT) {
                const int st3 = (u + 3) & 3;
                BAR_SYNC(1 + st3);          // slot free: readers of t-1 done
                load_stage4(gAh, gAl, gBh, gBl, Kdim, (t + 3) * 16,
                            smem4 + st3 * 4096, tid);
                CP_MBAR_ARRIVE(fb + 8 * st3);
            }

#pragma unroll
            for (int i = 0; i < 4; ++i)
#pragma unroll
                for (int j = 0; j < 4; ++j) {
                    mma_bf16(c[i][j], ah[i], bh[j]);
                    mma_bf16(c[i][j], ah[i], bl[j]);
                    mma_bf16(c[i][j], al[i], bh[j]);
                }

            BAR_ARRIVE(1 + u);              // read-done for this slot
        }
    }

    const int r  = lane >> 2;
    const int cc = (lane & 3) * 2;

    if (FUSED && z < 2) {
        __nv_bfloat16* oh = z ? kh : qh;
        __nv_bfloat16* ol = z ? kl : ql;
#pragma unroll
        for (int i = 0; i < 4; ++i)
#pragma unroll
            for (int j = 0; j < 4; ++j) {
                const int col = col0 + wx * 32 + j * 8 + cc;       // even
                const int pi  = (col & 63) >> 1;                   // rope pair idx
                const int m0r = row0 + wy * 64 + i * 16 + r;
                const int m1r = m0r + 8;
                float2 t0 = rope[(size_t)(m0r & (SS - 1)) * HALF + pi];
                float2 t1 = rope[(size_t)(m1r & (SS - 1)) * HALF + pi];
                uint32_t hh, ll;
                float re0 = c[i][j][0] * t0.x - c[i][j][1] * t0.y;
                float ro0 = c[i][j][0] * t0.y + c[i][j][1] * t0.x;
                split2(re0, ro0, hh, ll);
                *(uint32_t*)(oh + (size_t)m0r * D_MODEL + col) = hh;
                *(uint32_t*)(ol + (size_t)m0r * D_MODEL + col) = ll;
                float re1 = c[i][j][2] * t1.x - c[i][j][3] * t1.y;
                float ro1 = c[i][j][2] * t1.y + c[i][j][3] * t1.x;
                split2(re1, ro1, hh, ll);
                *(uint32_t*)(oh + (size_t)m1r * D_MODEL + col) = hh;
                *(uint32_t*)(ol + (size_t)m1r * D_MODEL + col) = ll;
            }
    } else {
#pragma unroll
        for (int i = 0; i < 4; ++i)
#pragma unroll
            for (int j = 0; j < 4; ++j) {
                float* cp = Cf + (size_t)(row0 + wy * 64 + i * 16 + r) * Ndim
                              + col0 + wx * 32 + j * 8 + cc;
                *(float2*)cp = make_float2(c[i][j][0], c[i][j][1]);
                *(float2*)(cp + 8 * (size_t)Ndim) = make_float2(c[i][j][2], c[i][j][3]);
            }
    }
}

// ---------------------------------------------------------------------------
// V transpose + split
// ---------------------------------------------------------------------------
__global__ void __launch_bounds__(256) vtrans_split_kernel(
    const float* __restrict__ v,
    __nv_bfloat16* __restrict__ vth, __nv_bfloat16* __restrict__ vtl)
{
    __shared__ float tile[64][65];
    const int tb = blockIdx.x;
    const int bh = blockIdx.y;
    const int b  = bh >> 4, h = bh & 15;
    const int tid = threadIdx.x;

#pragma unroll
    for (int i = 0; i < 4; ++i) {
        int e = tid + i * 256;
        int t = e >> 4;
        int d4 = (e & 15) * 4;
        float4 vv = *(const float4*)(v + (size_t)(b * SS + tb * 64 + t) * D_MODEL
                                       + h * DK + d4);
        tile[d4 + 0][t] = vv.x;
        tile[d4 + 1][t] = vv.y;
        tile[d4 + 2][t] = vv.z;
        tile[d4 + 3][t] = vv.w;
    }
    __syncthreads();

#pragma unroll
    for (int i = 0; i < 8; ++i) {
        int e = tid + i * 256;
        int d = e >> 5;
        int t2 = (e & 31) * 2;
        uint32_t hh, ll;
        split2(tile[d][t2], tile[d][t2 + 1], hh, ll);
        size_t dst = ((size_t)(bh * 64 + d)) * SS + tb * 64 + t2;
        *(uint32_t*)(vth + dst) = hh;
        *(uint32_t*)(vtl + dst) = ll;
    }
}

// ---------------------------------------------------------------------------
// Tensor-core flash attention (causal), bf16x3, 2 CTAs/SM.
// P hi/lo pack folded into the PV loop to cut live registers.
// ---------------------------------------------------------------------------
__device__ __forceinline__ void attn_load_tile(
    uint32_t* dsm, int nsb, int tid, int b, int kt, int hoff, size_t vrow0,
    const __nv_bfloat16* __restrict__ Kh, const __nv_bfloat16* __restrict__ Kl,
    const __nv_bfloat16* __restrict__ Vth, const __nv_bfloat16* __restrict__ Vtl)
{
#pragma unroll
    for (int i = 0; i < 8; ++i) {
        int c = tid + i * 256;
        if (c < 1024) {
            int arr = c >> 9, cc = c & 511;
            int t = cc >> 3, kq = cc & 7;
            int wd = ((((t >> 3) * 4 + (kq >> 1)) * 2 + (kq & 1)) << 5) + (t & 7) * 4;
            const __nv_bfloat16* src = (arr ? Kl : Kh)
                + (size_t)(b * SS + kt * 64 + t) * D_MODEL + hoff + kq * 8;
            CP_ASYNC16(smem_u32(dsm + nsb + arr * 2048 + wd), src);
        } else {
            int c2 = c - 1024;
            int arr = c2 >> 9, cc = c2 & 511;
            int d = cc >> 3, tq = cc & 7;
            int wd = ((((d >> 3) * 4 + (tq >> 1)) * 2 + (tq & 1)) << 5) + (d & 7) * 4;
            const __nv_bfloat16* src = (arr ? Vtl : Vth)
                + vrow0 + (size_t)d * SS + kt * 64 + tq * 8;
            CP_ASYNC16(smem_u32(dsm + nsb + 4096 + arr * 2048 + wd), src);
        }
    }
}

__global__ void __launch_bounds__(256, 2) attn_tc_kernel(
    const __nv_bfloat16* __restrict__ Qh, const __nv_bfloat16* __restrict__ Ql,
    const __nv_bfloat16* __restrict__ Kh, const __nv_bfloat16* __restrict__ Kl,
    const __nv_bfloat16* __restrict__ Vth, const __nv_bfloat16* __restrict__ Vtl,
    __nv_bfloat16* __restrict__ Oh, __nv_bfloat16* __restrict__ Ol)
{
    extern __shared__ uint32_t dsm[];   // 16384 u32 = 64KB

    const int qi  = (gridDim.x - 1) - blockIdx.x;   // big work first (LPT)
    const int h   = blockIdx.y;
    const int b   = blockIdx.z;
    const int tid = threadIdx.x;
    const int lane = tid & 31;
    const int w    = tid >> 5;

    const int tok0 = b * SS + qi * 128;
    const int hoff = h * DK;
    const size_t vrow0 = (size_t)((b * 16 + h) * 64) * SS;
    const int kt_last = qi * 2 + 1;

    // prologue: Q into stage1 region, tile0 into stage0
#pragma unroll
    for (int i = 0; i < 8; ++i) {
        int c   = tid + i * 256;
        int arr = c >> 10;
        int cc  = c & 1023;
        int m = cc >> 3, kq = cc & 7;
        int wd = ((((m >> 4) * 4 + (kq >> 1)) * 4 + ((m >> 3) & 1) + 2 * (kq & 1)) << 5)
                 + (m & 7) * 4;
        const __nv_bfloat16* src = (arr ? Ql : Qh)
            + (size_t)(tok0 + m) * D_MODEL + hoff + kq * 8;
        CP_ASYNC16(smem_u32(dsm + 8192 + arr * 4096 + wd), src);
    }
    attn_load_tile(dsm, 0, tid, b, 0, hoff, vrow0, Kh, Kl, Vth, Vtl);
    CP_COMMIT();
    CP_WAIT0();
    __syncthreads();

    uint32_t qfh[4][4], qfl[4][4];
#pragma unroll
    for (int ks = 0; ks < 4; ++ks)
#pragma unroll
        for (int r = 0; r < 4; ++r) {
            int wd = (((w * 4 + ks) * 4 + r) << 5) + lane;
            qfh[ks][r] = dsm[8192 + wd];
            qfl[ks][r] = dsm[12288 + wd];
        }
    __syncthreads();   // Q region now free (stage 1 overlays it)

    float acc[8][4];
#pragma unroll
    for (int j = 0; j < 8; ++j)
#pragma unroll
        for (int r = 0; r < 4; ++r) acc[j][r] = 0.f;
    float m0 = -1e30f, m1 = -1e30f, l0 = 0.f, l1 = 0.f;

    const int q0w = qi * 128 + w * 16;

    for (int kt = 0; kt <= kt_last; ++kt) {
        const int sb = (kt & 1) * 8192;
        CP_WAIT0();        // loads for kt complete
        __syncthreads();   // visibility + WAR guard for the issue below

        if (kt < kt_last) {
            attn_load_tile(dsm, ((kt + 1) & 1) * 8192, tid, b, kt + 1,
                           hoff, vrow0, Kh, Kl, Vth, Vtl);
            CP_COMMIT();
        }

        if (kt * 64 <= q0w + 15) {
            const uint32_t* sKh = dsm + sb;
            const uint32_t* sKl = dsm + sb + 2048;
            const uint32_t* sVh = dsm + sb + 4096;
            const uint32_t* sVl = dsm + sb + 6144;

            float s[8][4];
#pragma unroll
            for (int j = 0; j < 8; ++j)
#pragma unroll
                for (int r = 0; r < 4; ++r) s[j][r] = 0.f;

#pragma unroll
            for (int ks = 0; ks < 4; ++ks)
#pragma unroll
                for (int jn = 0; jn < 8; ++jn) {
                    int base = ((jn * 4 + ks) << 6) + lane;
                    uint32_t bh[2] = {sKh[base], sKh[base + 32]};
                    uint32_t bl[2] = {sKl[base], sKl[base + 32]};
                    mma_bf16(s[jn], qfh[ks], bh);
                    mma_bf16(s[jn], qfh[ks], bl);
                    mma_bf16(s[jn], qfl[ks], bh);
                }

#pragma unroll
            for (int j = 0; j < 8; ++j)
#pragma unroll
                for (int r = 0; r < 4; ++r) s[j][r] *= 0.125f;

            if (kt * 64 + 63 > q0w) {
                const int row0g = q0w + (lane >> 2);
                const int colbg = kt * 64 + 2 * (lane & 3);
#pragma unroll
                for (int jn = 0; jn < 8; ++jn) {
                    int c0 = colbg + jn * 8;
                    if (c0 > row0g)     s[jn][0] = -1e30f;
                    if (c0 + 1 > row0g) s[jn][1] = -1e30f;
                    if (c0 > row0g + 8)     s[jn][2] = -1e30f;
                    if (c0 + 1 > row0g + 8) s[jn][3] = -1e30f;
                }
            }

            float mx0 = -1e30f, mx1 = -1e30f;
#pragma unroll
            for (int j = 0; j < 8; ++j) {
                mx0 = fmaxf(mx0, fmaxf(s[j][0], s[j][1]));
                mx1 = fmaxf(mx1, fmaxf(s[j][2], s[j][3]));
            }
            mx0 = fmaxf(mx0, __shfl_xor_sync(0xffffffffu, mx0, 1));
            mx0 = fmaxf(mx0, __shfl_xor_sync(0xffffffffu, mx0, 2));
            mx1 = fmaxf(mx1, __shfl_xor_sync(0xffffffffu, mx1, 1));
            mx1 = fmaxf(mx1, __shfl_xor_sync(0xffffffffu, mx1, 2));

            float mn0 = fmaxf(m0, mx0), mn1 = fmaxf(m1, mx1);
            float al0 = __expf(m0 - mn0), al1 = __expf(m1 - mn1);
            m0 = mn0; m1 = mn1;

            float sum0 = 0.f, sum1 = 0.f;
#pragma unroll
            for (int j = 0; j < 8; ++j) {
                s[j][0] = __expf(s[j][0] - mn0);
                s[j][1] = __expf(s[j][1] - mn0);
                s[j][2] = __expf(s[j][2] - mn1);
                s[j][3] = __expf(s[j][3] - mn1);
                sum0 += s[j][0] + s[j][1];
                sum1 += s[j][2] + s[j][3];
            }
            sum0 += __shfl_xor_sync(0xffffffffu, sum0, 1);
            sum0 += __shfl_xor_sync(0xffffffffu, sum0, 2);
            sum1 += __shfl_xor_sync(0xffffffffu, sum1, 1);
            sum1 += __shfl_xor_sync(0xffffffffu, sum1, 2);
            l0 = l0 * al0 + sum0;
            l1 = l1 * al1 + sum1;

#pragma unroll
            for (int j = 0; j < 8; ++j) {
                acc[j][0] *= al0; acc[j][1] *= al0;
                acc[j][2] *= al1; acc[j][3] *= al1;
            }

            // P pack folded into the PV loop: one 4-reg frag pair live at a time
#pragma unroll
            for (int kk = 0; kk < 4; ++kk) {
                uint32_t ph4[4], pl4[4];
                split2(s[2 * kk][0],     s[2 * kk][1],     ph4[0], pl4[0]);
                split2(s[2 * kk][2],     s[2 * kk][3],     ph4[1], pl4[1]);
                split2(s[2 * kk + 1][0], s[2 * kk + 1][1], ph4[2], pl4[2]);
                split2(s[2 * kk + 1][2], s[2 * kk + 1][3], ph4[3], pl4[3]);
#pragma unroll
                for (int jd = 0; jd < 8; ++jd) {
                    int base = ((jd * 4 + kk) << 6) + lane;
                    uint32_t vh[2] = {sVh[base], sVh[base + 32]};
                    uint32_t vl[2] = {sVl[base], sVl[base + 32]};
                    mma_bf16(acc[jd], ph4, vh);
                    mma_bf16(acc[jd], ph4, vl);
                    mma_bf16(acc[jd], pl4, vh);
                }
            }
        }
        // no trailing sync: next iteration's leading sync is the WAR guard
    }

    const float inv0 = 1.f / l0, inv1 = 1.f / l1;
    const int r  = lane >> 2;
    const int cc = 2 * (lane & 3);
    const size_t r0 = (size_t)(tok0 + w * 16 + r) * D_MODEL + hoff;
    const size_t r1 = r0 + 8 * (size_t)D_MODEL;
#pragma unroll
    for (int jd = 0; jd < 8; ++jd) {
        uint32_t hh, ll;
        split2(acc[jd][0] * inv0, acc[jd][1] * inv0, hh, ll);
        *(uint32_t*)(Oh + r0 + jd * 8 + cc) = hh;
        *(uint32_t*)(Ol + r0 + jd * 8 + cc) = ll;
        split2(acc[jd][2] * inv1, acc[jd][3] * inv1, hh, ll);
        *(uint32_t*)(Oh + r1 + jd * 8 + cc) = hh;
        *(uint32_t*)(Ol + r1 + jd * 8 + cc) = ll;
    }
}

// ---------------------------------------------------------------------------
extern "C" void kernel_launch(void* const* d_in, const int* in_sizes, int n_in,
                              void* d_out, int out_size)
{
    const float* wq  = (const float*)d_in[0];
    const float* wk  = (const float*)d_in[1];
    const float* wv  = (const float*)d_in[2];
    const float* wo  = (const float*)d_in[3];
    const float* x   = (const float*)d_in[4];
    const int*   pos = (const int*)d_in[5];
    float* out = (float*)d_out;

    float* dv;
    cudaGetSymbolAddress((void**)&dv, g_v);
    __nv_bfloat16 *xh, *xl, *ath, *atl, *wh, *wl;
    __nv_bfloat16 *qh, *ql, *kh, *kl, *vth, *vtl;
    float2* ropet;
    cudaGetSymbolAddress((void**)&xh,  g_xh);
    cudaGetSymbolAddress((void**)&xl,  g_xl);
    cudaGetSymbolAddress((void**)&ath, g_ah);
    cudaGetSymbolAddress((void**)&atl, g_al);
    cudaGetSymbolAddress((void**)&wh,  g_wh);
    cudaGetSymbolAddress((void**)&wl,  g_wl);
    cudaGetSymbolAddress((void**)&qh,  g_qh);
    cudaGetSymbolAddress((void**)&ql,  g_ql);
    cudaGetSymbolAddress((void**)&kh,  g_kh);
    cudaGetSymbolAddress((void**)&kl,  g_kl);
    cudaGetSymbolAddress((void**)&vth, g_vth);
    cudaGetSymbolAddress((void**)&vtl, g_vtl);
    cudaGetSymbolAddress((void**)&ropet, g_rope);

    const size_t WSZ = (size_t)D_MODEL * D_MODEL;
    const int n4x = (int)((size_t)MM * D_MODEL / 4);
    const int n4w = (int)(WSZ / 4);

    rope_table_kernel<<<(SS * HALF) / 256, 256>>>(pos, ropet);
    split_bf16_kernel<<<(n4x + 255) / 256, 256>>>(x, xh, xl, n4x);
    split4_bf16_kernel<<<dim3((n4w + 255) / 256, 4), 256>>>(
        wq, wk, wv, wo, wh, wl, n4w);

    cudaFuncSetAttribute(gemm_bf16x3_nt<1>,
                         cudaFuncAttributeMaxDynamicSharedMemorySize, 65536);
    cudaFuncSetAttribute(gemm_bf16x3_nt<0>,
                         cudaFuncAttributeMaxDynamicSharedMemorySize, 65536);

    // fused QKV: z=0 -> rope-split q, z=1 -> rope-split k, z=2 -> fp32 v
    gemm_bf16x3_nt<1><<<dim3(D_MODEL / 128, MM / 128, 3), 256, 65536>>>(
        xh, xl, wh, wl, dv, qh, ql, kh, kl, ropet, MM, D_MODEL, D_MODEL);

    vtrans_split_kernel<<<dim3(SS / 64, BB * NUM_HEADS), 256>>>(dv, vth, vtl);

    cudaFuncSetAttribute(attn_tc_kernel,
                         cudaFuncAttributeMaxDynamicSharedMemorySize, 65536);
    attn_tc_kernel<<<dim3(SS / 128, NUM_HEADS, BB), 256, 65536>>>(
        qh, ql, kh, kl, vth, vtl, ath, atl);

    // O projection: plain fp32 epilogue, weight slot 3
    gemm_bf16x3_nt<0><<<dim3(D_MODEL / 128, MM / 128, 1), 256, 65536>>>(
        ath, atl, wh + 3 * WSZ, wl + 3 * WSZ, out,
        nullptr, nullptr, nullptr, nullptr, ropet, MM, D_MODEL, D_MODEL);
}

// round 13
// speedup vs baseline: 1.3238x; 1.3238x over previous
#include <cuda_runtime.h>
#include <cuda_fp16.h>
#include <math.h>
#include <stdint.h>

#define D_MODEL 1024
#define NUM_HEADS 16
#define DK 64
#define HALF 32
#define BB 4
#define SS 2048
#define MM (BB * SS)           // 8192 tokens
#define LOG2_THETA 13.287712379549449f   // log2(10000)

// ---------------- scratch (device globals: no allocation allowed) ----------
__device__ float g_v[(size_t)MM * D_MODEL];            // V projection (fp32)

__device__ __half g_xh[(size_t)MM * D_MODEL];
__device__ __half g_xl[(size_t)MM * D_MODEL];
__device__ __half g_ah[(size_t)MM * D_MODEL];          // attention out hi
__device__ __half g_al[(size_t)MM * D_MODEL];          // attention out lo
__device__ __half g_wf[4][(size_t)D_MODEL * D_MODEL];  // weights single fp16

__device__ __half g_qh[(size_t)MM * D_MODEL];
__device__ __half g_ql[(size_t)MM * D_MODEL];
__device__ __half g_kf[(size_t)MM * D_MODEL];          // K single fp16
__device__ __half g_vtf[(size_t)MM * D_MODEL];         // V^T single fp16

__device__ float2 g_rope[(size_t)SS * HALF];           // {cos, sin} table

// ---------------------------------------------------------------------------
__device__ __forceinline__ uint32_t smem_u32(const void* p) {
    return (uint32_t)__cvta_generic_to_shared(p);
}
#define CP_ASYNC16(dst, src) \
    asm volatile("cp.async.cg.shared.global [%0], [%1], 16;\n" :: "r"(dst), "l"(src))
#define CP_COMMIT() asm volatile("cp.async.commit_group;\n" ::: "memory")
#define CP_WAIT2()  asm volatile("cp.async.wait_group 2;\n" ::: "memory")
#define CP_WAIT1()  asm volatile("cp.async.wait_group 1;\n" ::: "memory")
#define CP_WAIT0()  asm volatile("cp.async.wait_group 0;\n" ::: "memory")

__device__ __forceinline__ void mma_fp16(float c[4], const uint32_t a[4],
                                         const uint32_t b[2]) {
    asm volatile(
        "mma.sync.aligned.m16n8k16.row.col.f32.f16.f16.f32 "
        "{%0,%1,%2,%3}, {%4,%5,%6,%7}, {%8,%9}, {%0,%1,%2,%3};\n"
        : "+f"(c[0]), "+f"(c[1]), "+f"(c[2]), "+f"(c[3])
        : "r"(a[0]), "r"(a[1]), "r"(a[2]), "r"(a[3]), "r"(b[0]), "r"(b[1]));
}

// fp16 hi/lo split of a float pair (A-side operands: ~22-bit effective)
__device__ __forceinline__ void split2h(float x, float y, uint32_t& hi, uint32_t& lo) {
    __half2 h = __floats2half2_rn(x, y);
    float hx = __low2float(h), hy = __high2float(h);
    __half2 l = __floats2half2_rn(x - hx, y - hy);
    hi = *(uint32_t*)&h;
    lo = *(uint32_t*)&l;
}
__device__ __forceinline__ uint32_t round2h(float x, float y) {
    __half2 h = __floats2half2_rn(x, y);
    return *(uint32_t*)&h;
}

// ---------------------------------------------------------------------------
// RoPE cos/sin table
// ---------------------------------------------------------------------------
__global__ void __launch_bounds__(256) rope_table_kernel(
    const int* __restrict__ pos, float2* __restrict__ tab)
{
    int idx = blockIdx.x * blockDim.x + threadIdx.x;   // < SS*HALF
    int s = idx >> 5, i = idx & (HALF - 1);
    float p = (float)pos[s];
    float inv_freq = exp2f(-(float)i * (LOG2_THETA / (float)HALF));
    float sn, cs;
    sincosf(p * inv_freq, &sn, &cs);
    tab[idx] = make_float2(cs, sn);
}

// ---------------------------------------------------------------------------
// fp32 -> fp16 hi/lo split (x) and fp32 -> fp16 round (weights x4)
// ---------------------------------------------------------------------------
__global__ void __launch_bounds__(256) split_h_kernel(
    const float* __restrict__ src, __half* __restrict__ hi,
    __half* __restrict__ lo, int n4)
{
    int i = blockIdx.x * blockDim.x + threadIdx.x;
    if (i >= n4) return;
    float4 v = ((const float4*)src)[i];
    uint32_t h0, l0, h1, l1;
    split2h(v.x, v.y, h0, l0);
    split2h(v.z, v.w, h1, l1);
    ((uint32_t*)hi)[i * 2 + 0] = h0;
    ((uint32_t*)hi)[i * 2 + 1] = h1;
    ((uint32_t*)lo)[i * 2 + 0] = l0;
    ((uint32_t*)lo)[i * 2 + 1] = l1;
}

__global__ void __launch_bounds__(256) round4_h_kernel(
    const float* __restrict__ w0, const float* __restrict__ w1,
    const float* __restrict__ w2, const float* __restrict__ w3,
    __half* __restrict__ outB, int n4)
{
    int i = blockIdx.x * blockDim.x + threadIdx.x;
    if (i >= n4) return;
    const int zz = blockIdx.y;
    const float* src = (zz == 0) ? w0 : (zz == 1) ? w1 : (zz == 2) ? w2 : w3;
    __half* dst = outB + (size_t)zz * D_MODEL * D_MODEL;
    float4 v = ((const float4*)src)[i];
    ((uint32_t*)dst)[i * 2 + 0] = round2h(v.x, v.y);
    ((uint32_t*)dst)[i * 2 + 1] = round2h(v.z, v.w);
}

// ---------------------------------------------------------------------------
// fp16x2 mma.sync GEMM (NT): C = (Ah+Al)[M,K] * Bh[N,K]^T   (B single fp16)
// 128x128 tile, BK=16, 256 threads (8 warps, 2x4), warp tile 64x32.
// 4-stage cp.async, single sync per k-step (R9-validated loop).
// 2 MMAs per (i,j): ah*b + al*b.  Stage = Ah|Al|B, 12KB.
// FUSED=1 (QKV): z=0 -> rope+split Q; z=1 -> rope+round K; z=2 -> fp32 V.
// FUSED=0 (O-proj): plain fp32 epilogue.
// ---------------------------------------------------------------------------
#define GSTG 3072   // u32 per stage

__device__ __forceinline__ void load_stage3(
    const __half* __restrict__ gAh, const __half* __restrict__ gAl,
    const __half* __restrict__ gB,
    int Kdim, int k0, uint32_t* sb, int tid)
{
    const int m = tid >> 1;
    const int q = tid & 1;
    const size_t src = (size_t)m * Kdim + k0 + q * 8;
    const int aw = ((((m >> 4) * 4 + ((m >> 3) & 1) + 2 * q)) << 5) + (m & 7) * 4;
    const int bw = ((((m >> 3) * 2 + q)) << 5) + (m & 7) * 4;
    CP_ASYNC16(smem_u32(sb + aw),        gAh + src);
    CP_ASYNC16(smem_u32(sb + 1024 + aw), gAl + src);
    CP_ASYNC16(smem_u32(sb + 2048 + bw), gB + src);
}

template <int FUSED>
__global__ void __launch_bounds__(256) gemm_fp16x2_nt(
    const __half* __restrict__ Ah, const __half* __restrict__ Al,
    const __half* __restrict__ WB,
    float* __restrict__ Cf,
    __half* __restrict__ qh, __half* __restrict__ ql,
    __half* __restrict__ kf,
    const float2* __restrict__ rope,
    int Mdim, int Ndim, int Kdim)
{
    extern __shared__ uint32_t smem4[];   // 4 stages x 3072 u32 = 48KB

    const int tid  = threadIdx.x;
    const int lane = tid & 31;
    const int warp = tid >> 5;
    const int wy   = warp >> 2;
    const int wx   = warp & 3;
    const int row0 = blockIdx.y * 128;
    const int col0 = blockIdx.x * 128;
    const int z    = blockIdx.z;
    const size_t zw = (size_t)z * D_MODEL * D_MODEL;

    const __half* gAh = Ah + (size_t)row0 * Kdim;
    const __half* gAl = Al + (size_t)row0 * Kdim;
    const __half* gB  = WB + zw + (size_t)col0 * Kdim;

    float c[4][4][4];
#pragma unroll
    for (int i = 0; i < 4; ++i)
#pragma unroll
        for (int j = 0; j < 4; ++j)
#pragma unroll
            for (int r = 0; r < 4; ++r) c[i][j][r] = 0.f;

    const int NT = Kdim / 16;             // 64
    load_stage3(gAh, gAl, gB, Kdim, 0,  smem4,            tid); CP_COMMIT();
    load_stage3(gAh, gAl, gB, Kdim, 16, smem4 + GSTG,     tid); CP_COMMIT();
    load_stage3(gAh, gAl, gB, Kdim, 32, smem4 + 2 * GSTG, tid); CP_COMMIT();

    for (int t = 0; t < NT; ++t) {
        if (t < NT - 2)      { CP_WAIT2(); }
        else if (t < NT - 1) { CP_WAIT1(); }
        else                 { CP_WAIT0(); }
        __syncthreads();   // data visibility + WAR guard for the issue below

        if (t + 3 < NT) {
            load_stage3(gAh, gAl, gB, Kdim, (t + 3) * 16,
                        smem4 + ((t + 3) & 3) * GSTG, tid);
            CP_COMMIT();
        }

        const uint32_t* sb  = smem4 + (t & 3) * GSTG;
        const uint32_t* pAh = sb;
        const uint32_t* pAl = sb + 1024;
        const uint32_t* pB  = sb + 2048;

        uint32_t ah[4][4], al[4][4], b[4][2];
#pragma unroll
        for (int i = 0; i < 4; ++i) {
            const int base = (((wy * 4 + i) * 4) << 5) + lane;
#pragma unroll
            for (int r = 0; r < 4; ++r) {
                ah[i][r] = pAh[base + (r << 5)];
                al[i][r] = pAl[base + (r << 5)];
            }
        }
#pragma unroll
        for (int j = 0; j < 4; ++j) {
            const int base = (((wx * 4 + j) * 2) << 5) + lane;
#pragma unroll
            for (int r = 0; r < 2; ++r) b[j][r] = pB[base + (r << 5)];
        }

#pragma unroll
        for (int i = 0; i < 4; ++i)
#pragma unroll
            for (int j = 0; j < 4; ++j) {
                mma_fp16(c[i][j], ah[i], b[j]);
                mma_fp16(c[i][j], al[i], b[j]);
            }
    }

    const int r  = lane >> 2;
    const int cc = (lane & 3) * 2;

    if (FUSED && z < 2) {
#pragma unroll
        for (int i = 0; i < 4; ++i)
#pragma unroll
            for (int j = 0; j < 4; ++j) {
                const int col = col0 + wx * 32 + j * 8 + cc;       // even
                const int pi  = (col & 63) >> 1;                   // rope pair idx
                const int m0r = row0 + wy * 64 + i * 16 + r;
                const int m1r = m0r + 8;
                float2 t0 = rope[(size_t)(m0r & (SS - 1)) * HALF + pi];
                float2 t1 = rope[(size_t)(m1r & (SS - 1)) * HALF + pi];
                float re0 = c[i][j][0] * t0.x - c[i][j][1] * t0.y;
                float ro0 = c[i][j][0] * t0.y + c[i][j][1] * t0.x;
                float re1 = c[i][j][2] * t1.x - c[i][j][3] * t1.y;
                float ro1 = c[i][j][2] * t1.y + c[i][j][3] * t1.x;
                if (z == 0) {
                    uint32_t hh, ll;
                    split2h(re0, ro0, hh, ll);
                    *(uint32_t*)(qh + (size_t)m0r * D_MODEL + col) = hh;
                    *(uint32_t*)(ql + (size_t)m0r * D_MODEL + col) = ll;
                    split2h(re1, ro1, hh, ll);
                    *(uint32_t*)(qh + (size_t)m1r * D_MODEL + col) = hh;
                    *(uint32_t*)(ql + (size_t)m1r * D_MODEL + col) = ll;
                } else {
                    *(uint32_t*)(kf + (size_t)m0r * D_MODEL + col) = round2h(re0, ro0);
                    *(uint32_t*)(kf + (size_t)m1r * D_MODEL + col) = round2h(re1, ro1);
                }
            }
    } else {
#pragma unroll
        for (int i = 0; i < 4; ++i)
#pragma unroll
            for (int j = 0; j < 4; ++j) {
                float* cp = Cf + (size_t)(row0 + wy * 64 + i * 16 + r) * Ndim
                              + col0 + wx * 32 + j * 8 + cc;
                *(float2*)cp = make_float2(c[i][j][0], c[i][j][1]);
                *(float2*)(cp + 8 * (size_t)Ndim) = make_float2(c[i][j][2], c[i][j][3]);
            }
    }
}

// ---------------------------------------------------------------------------
// V transpose + round: fp32 [b*S+t][1024] -> vtf fp16 [(b*16+h)*64+d][S]
// ---------------------------------------------------------------------------
__global__ void __launch_bounds__(256) vtrans_round_kernel(
    const float* __restrict__ v, __half* __restrict__ vtf)
{
    __shared__ float tile[64][65];
    const int tb = blockIdx.x;
    const int bh = blockIdx.y;
    const int b  = bh >> 4, h = bh & 15;
    const int tid = threadIdx.x;

#pragma unroll
    for (int i = 0; i < 4; ++i) {
        int e = tid + i * 256;
        int t = e >> 4;
        int d4 = (e & 15) * 4;
        float4 vv = *(const float4*)(v + (size_t)(b * SS + tb * 64 + t) * D_MODEL
                                       + h * DK + d4);
        tile[d4 + 0][t] = vv.x;
        tile[d4 + 1][t] = vv.y;
        tile[d4 + 2][t] = vv.z;
        tile[d4 + 3][t] = vv.w;
    }
    __syncthreads();

#pragma unroll
    for (int i = 0; i < 8; ++i) {
        int e = tid + i * 256;
        int d = e >> 5;
        int t2 = (e & 31) * 2;
        size_t dst = ((size_t)(bh * 64 + d)) * SS + tb * 64 + t2;
        *(uint32_t*)(vtf + dst) = round2h(tile[d][t2], tile[d][t2 + 1]);
    }
}

// ---------------------------------------------------------------------------
// Tensor-core flash attention (causal), fp16x2 (Q split / K single,
// P split / V single). 2 MMAs per fragment pair. Smem: 2 stages x 16KB
// (K 8KB | V 8KB) + Q hi/lo 32KB = 64KB.
// ---------------------------------------------------------------------------
__device__ __forceinline__ void attn_load_tile(
    uint32_t* dsm, int nsb, int tid, int b, int kt, int hoff, size_t vrow0,
    const __half* __restrict__ Kf, const __half* __restrict__ Vtf)
{
#pragma unroll
    for (int i = 0; i < 4; ++i) {
        int c = tid + i * 256;
        if (c < 512) {
            int t = c >> 3, kq = c & 7;
            int wd = ((((t >> 3) * 4 + (kq >> 1)) * 2 + (kq & 1)) << 5) + (t & 7) * 4;
            const __half* src = Kf
                + (size_t)(b * SS + kt * 64 + t) * D_MODEL + hoff + kq * 8;
            CP_ASYNC16(smem_u32(dsm + nsb + wd), src);
        } else {
            int c2 = c - 512;
            int d = c2 >> 3, tq = c2 & 7;
            int wd = ((((d >> 3) * 4 + (tq >> 1)) * 2 + (tq & 1)) << 5) + (d & 7) * 4;
            const __half* src = Vtf + vrow0 + (size_t)d * SS + kt * 64 + tq * 8;
            CP_ASYNC16(smem_u32(dsm + nsb + 2048 + wd), src);
        }
    }
}

__global__ void __launch_bounds__(256) attn_tc_kernel(
    const __half* __restrict__ Qh, const __half* __restrict__ Ql,
    const __half* __restrict__ Kf, const __half* __restrict__ Vtf,
    __half* __restrict__ Oh, __half* __restrict__ Ol)
{
    extern __shared__ uint32_t dsm[];   // 16384 u32 = 64KB

    const int qi  = (gridDim.x - 1) - blockIdx.x;   // big work first (LPT)
    const int h   = blockIdx.y;
    const int b   = blockIdx.z;
    const int tid = threadIdx.x;
    const int lane = tid & 31;
    const int w    = tid >> 5;

    const int tok0 = b * SS + qi * 128;
    const int hoff = h * DK;
    const size_t vrow0 = (size_t)((b * 16 + h) * 64) * SS;
    const int kt_last = qi * 2 + 1;

    // prologue: Q hi/lo into 8192.. region, tile0 into stage0
#pragma unroll
    for (int i = 0; i < 8; ++i) {
        int c   = tid + i * 256;              // 0..2047
        int arr = c >> 10;                    // 0 hi, 1 lo
        int cc  = c & 1023;
        int m = cc >> 3, kq = cc & 7;
        int wd = ((((m >> 4) * 4 + (kq >> 1)) * 4 + ((m >> 3) & 1) + 2 * (kq & 1)) << 5)
                 + (m & 7) * 4;
        const __half* src = (arr ? Ql : Qh)
            + (size_t)(tok0 + m) * D_MODEL + hoff + kq * 8;
        CP_ASYNC16(smem_u32(dsm + 8192 + arr * 4096 + wd), src);
    }
    attn_load_tile(dsm, 0, tid, b, 0, hoff, vrow0, Kf, Vtf);
    CP_COMMIT();
    CP_WAIT0();
    __syncthreads();

    uint32_t qfh[4][4], qfl[4][4];
#pragma unroll
    for (int ks = 0; ks < 4; ++ks)
#pragma unroll
        for (int r = 0; r < 4; ++r) {
            int wd = (((w * 4 + ks) * 4 + r) << 5) + lane;
            qfh[ks][r] = dsm[8192 + wd];
            qfl[ks][r] = dsm[12288 + wd];
        }
    __syncthreads();

    float acc[8][4];
#pragma unroll
    for (int j = 0; j < 8; ++j)
#pragma unroll
        for (int r = 0; r < 4; ++r) acc[j][r] = 0.f;
    float m0 = -1e30f, m1 = -1e30f, l0 = 0.f, l1 = 0.f;

    const int q0w = qi * 128 + w * 16;

    for (int kt = 0; kt <= kt_last; ++kt) {
        const int sb = (kt & 1) * 4096;
        CP_WAIT0();        // loads for kt complete
        __syncthreads();   // visibility + WAR guard for the issue below

        if (kt < kt_last) {
            attn_load_tile(dsm, ((kt + 1) & 1) * 4096, tid, b, kt + 1,
                           hoff, vrow0, Kf, Vtf);
            CP_COMMIT();
        }

        if (kt * 64 <= q0w + 15) {
            const uint32_t* sK = dsm + sb;
            const uint32_t* sV = dsm + sb + 2048;

            float s[8][4];
#pragma unroll
            for (int j = 0; j < 8; ++j)
#pragma unroll
                for (int r = 0; r < 4; ++r) s[j][r] = 0.f;

#pragma unroll
            for (int ks = 0; ks < 4; ++ks)
#pragma unroll
                for (int jn = 0; jn < 8; ++jn) {
                    int base = ((jn * 4 + ks) << 6) + lane;
                    uint32_t bf[2] = {sK[base], sK[base + 32]};
                    mma_fp16(s[jn], qfh[ks], bf);
                    mma_fp16(s[jn], qfl[ks], bf);
                }

#pragma unroll
            for (int j = 0; j < 8; ++j)
#pragma unroll
                for (int r = 0; r < 4; ++r) s[j][r] *= 0.125f;

            if (kt * 64 + 63 > q0w) {
                const int row0g = q0w + (lane >> 2);
                const int colbg = kt * 64 + 2 * (lane & 3);
#pragma unroll
                for (int jn = 0; jn < 8; ++jn) {
                    int c0 = colbg + jn * 8;
                    if (c0 > row0g)     s[jn][0] = -1e30f;
                    if (c0 + 1 > row0g) s[jn][1] = -1e30f;
                    if (c0 > row0g + 8)     s[jn][2] = -1e30f;
                    if (c0 + 1 > row0g + 8) s[jn][3] = -1e30f;
                }
            }

            float mx0 = -1e30f, mx1 = -1e30f;
#pragma unroll
            for (int j = 0; j < 8; ++j) {
                mx0 = fmaxf(mx0, fmaxf(s[j][0], s[j][1]));
                mx1 = fmaxf(mx1, fmaxf(s[j][2], s[j][3]));
            }
            mx0 = fmaxf(mx0, __shfl_xor_sync(0xffffffffu, mx0, 1));
            mx0 = fmaxf(mx0, __shfl_xor_sync(0xffffffffu, mx0, 2));
            mx1 = fmaxf(mx1, __shfl_xor_sync(0xffffffffu, mx1, 1));
            mx1 = fmaxf(mx1, __shfl_xor_sync(0xffffffffu, mx1, 2));

            float mn0 = fmaxf(m0, mx0), mn1 = fmaxf(m1, mx1);
            float al0 = __expf(m0 - mn0), al1 = __expf(m1 - mn1);
            m0 = mn0; m1 = mn1;

            float sum0 = 0.f, sum1 = 0.f;
#pragma unroll
            for (int j = 0; j < 8; ++j) {
                s[j][0] = __expf(s[j][0] - mn0);
                s[j][1] = __expf(s[j][1] - mn0);
                s[j][2] = __expf(s[j][2] - mn1);
                s[j][3] = __expf(s[j][3] - mn1);
                sum0 += s[j][0] + s[j][1];
                sum1 += s[j][2] + s[j][3];
            }
            sum0 += __shfl_xor_sync(0xffffffffu, sum0, 1);
            sum0 += __shfl_xor_sync(0xffffffffu, sum0, 2);
            sum1 += __shfl_xor_sync(0xffffffffu, sum1, 1);
            sum1 += __shfl_xor_sync(0xffffffffu, sum1, 2);
            l0 = l0 * al0 + sum0;
            l1 = l1 * al1 + sum1;

#pragma unroll
            for (int j = 0; j < 8; ++j) {
                acc[j][0] *= al0; acc[j][1] *= al0;
                acc[j][2] *= al1; acc[j][3] *= al1;
            }

            // P split fp16 (hi/lo) x V single: 2 MMAs per (kk, jd)
#pragma unroll
            for (int kk = 0; kk < 4; ++kk) {
                uint32_t ph4[4], pl4[4];
                split2h(s[2 * kk][0],     s[2 * kk][1],     ph4[0], pl4[0]);
                split2h(s[2 * kk][2],     s[2 * kk][3],     ph4[1], pl4[1]);
                split2h(s[2 * kk + 1][0], s[2 * kk + 1][1], ph4[2], pl4[2]);
                split2h(s[2 * kk + 1][2], s[2 * kk + 1][3], ph4[3], pl4[3]);
#pragma unroll
                for (int jd = 0; jd < 8; ++jd) {
                    int base = ((jd * 4 + kk) << 6) + lane;
                    uint32_t vf[2] = {sV[base], sV[base + 32]};
                    mma_fp16(acc[jd], ph4, vf);
                    mma_fp16(acc[jd], pl4, vf);
                }
            }
        }
        // no trailing sync: next iteration's leading sync is the WAR guard
    }

    // epilogue: normalize + fp16 split (input of O-projection)
    const float inv0 = 1.f / l0, inv1 = 1.f / l1;
    const int r  = lane >> 2;
    const int cc = 2 * (lane & 3);
    const size_t r0 = (size_t)(tok0 + w * 16 + r) * D_MODEL + hoff;
    const size_t r1 = r0 + 8 * (size_t)D_MODEL;
#pragma unroll
    for (int jd = 0; jd < 8; ++jd) {
        uint32_t hh, ll;
        split2h(acc[jd][0] * inv0, acc[jd][1] * inv0, hh, ll);
        *(uint32_t*)(Oh + r0 + jd * 8 + cc) = hh;
        *(uint32_t*)(Ol + r0 + jd * 8 + cc) = ll;
        split2h(acc[jd][2] * inv1, acc[jd][3] * inv1, hh, ll);
        *(uint32_t*)(Oh + r1 + jd * 8 + cc) = hh;
        *(uint32_t*)(Ol + r1 + jd * 8 + cc) = ll;
    }
}

// ---------------------------------------------------------------------------
extern "C" void kernel_launch(void* const* d_in, const int* in_sizes, int n_in,
                              void* d_out, int out_size)
{
    const float* wq  = (const float*)d_in[0];
    const float* wk  = (const float*)d_in[1];
    const float* wv  = (const float*)d_in[2];
    const float* wo  = (const float*)d_in[3];
    const float* x   = (const float*)d_in[4];
    const int*   pos = (const int*)d_in[5];
    float* out = (float*)d_out;

    float* dv;
    cudaGetSymbolAddress((void**)&dv, g_v);
    __half *xh, *xl, *ath, *atl, *wf;
    __half *qh, *ql, *kf, *vtf;
    float2* ropet;
    cudaGetSymbolAddress((void**)&xh,  g_xh);
    cudaGetSymbolAddress((void**)&xl,  g_xl);
    cudaGetSymbolAddress((void**)&ath, g_ah);
    cudaGetSymbolAddress((void**)&atl, g_al);
    cudaGetSymbolAddress((void**)&wf,  g_wf);
    cudaGetSymbolAddress((void**)&qh,  g_qh);
    cudaGetSymbolAddress((void**)&ql,  g_ql);
    cudaGetSymbolAddress((void**)&kf,  g_kf);
    cudaGetSymbolAddress((void**)&vtf, g_vtf);
    cudaGetSymbolAddress((void**)&ropet, g_rope);

    const size_t WSZ = (size_t)D_MODEL * D_MODEL;
    const int n4x = (int)((size_t)MM * D_MODEL / 4);
    const int n4w = (int)(WSZ / 4);

    rope_table_kernel<<<(SS * HALF) / 256, 256>>>(pos, ropet);
    split_h_kernel<<<(n4x + 255) / 256, 256>>>(x, xh, xl, n4x);
    round4_h_kernel<<<dim3((n4w + 255) / 256, 4), 256>>>(wq, wk, wv, wo, wf, n4w);

    cudaFuncSetAttribute(gemm_fp16x2_nt<1>,
                         cudaFuncAttributeMaxDynamicSharedMemorySize, 4 * GSTG * 4);
    cudaFuncSetAttribute(gemm_fp16x2_nt<0>,
                         cudaFuncAttributeMaxDynamicSharedMemorySize, 4 * GSTG * 4);

    // fused QKV: z=0 -> rope-split Q, z=1 -> rope-round K, z=2 -> fp32 V
    gemm_fp16x2_nt<1><<<dim3(D_MODEL / 128, MM / 128, 3), 256, 4 * GSTG * 4>>>(
        xh, xl, wf, dv, qh, ql, kf, ropet, MM, D_MODEL, D_MODEL);

    vtrans_round_kernel<<<dim3(SS / 64, BB * NUM_HEADS), 256>>>(dv, vtf);

    cudaFuncSetAttribute(attn_tc_kernel,
                         cudaFuncAttributeMaxDynamicSharedMemorySize, 65536);
    attn_tc_kernel<<<dim3(SS / 128, NUM_HEADS, BB), 256, 65536>>>(
        qh, ql, kf, vtf, ath, atl);

    // O projection: plain fp32 epilogue, weight slot 3
    gemm_fp16x2_nt<0><<<dim3(D_MODEL / 128, MM / 128, 1), 256, 4 * GSTG * 4>>>(
        ath, atl, wf + 3 * WSZ, out, nullptr, nullptr, nullptr,
        ropet, MM, D_MODEL, D_MODEL);
}

// round 14
// speedup vs baseline: 2.0463x; 1.5457x over previous
#include <cuda_runtime.h>
#include <cuda_fp16.h>
#include <math.h>
#include <stdint.h>

#define D_MODEL 1024
#define NUM_HEADS 16
#define DK 64
#define HALF 32
#define BB 4
#define SS 2048
#define MM (BB * SS)           // 8192 tokens
#define LOG2_THETA 13.287712379549449f   // log2(10000)

// ---------------- scratch (device globals: no allocation allowed) ----------
__device__ float g_v[(size_t)MM * D_MODEL];            // V projection (fp32)

__device__ __half g_xf[(size_t)MM * D_MODEL];          // x fp16
__device__ __half g_af[(size_t)MM * D_MODEL];          // attention out fp16
__device__ __half g_wf[4][(size_t)D_MODEL * D_MODEL];  // weights fp16

__device__ __half g_qf[(size_t)MM * D_MODEL];          // Q (roped) fp16
__device__ __half g_kf[(size_t)MM * D_MODEL];          // K (roped) fp16
__device__ __half g_vtf[(size_t)MM * D_MODEL];         // V^T fp16

__device__ float2 g_rope[(size_t)SS * HALF];           // {cos, sin} table

// ---------------------------------------------------------------------------
__device__ __forceinline__ uint32_t smem_u32(const void* p) {
    return (uint32_t)__cvta_generic_to_shared(p);
}
#define CP_ASYNC16(dst, src) \
    asm volatile("cp.async.cg.shared.global [%0], [%1], 16;\n" :: "r"(dst), "l"(src))
#define CP_COMMIT() asm volatile("cp.async.commit_group;\n" ::: "memory")
#define CP_WAIT2()  asm volatile("cp.async.wait_group 2;\n" ::: "memory")
#define CP_WAIT1()  asm volatile("cp.async.wait_group 1;\n" ::: "memory")
#define CP_WAIT0()  asm volatile("cp.async.wait_group 0;\n" ::: "memory")

__device__ __forceinline__ void mma_fp16(float c[4], const uint32_t a[4],
                                         const uint32_t b[2]) {
    asm volatile(
        "mma.sync.aligned.m16n8k16.row.col.f32.f16.f16.f32 "
        "{%0,%1,%2,%3}, {%4,%5,%6,%7}, {%8,%9}, {%0,%1,%2,%3};\n"
        : "+f"(c[0]), "+f"(c[1]), "+f"(c[2]), "+f"(c[3])
        : "r"(a[0]), "r"(a[1]), "r"(a[2]), "r"(a[3]), "r"(b[0]), "r"(b[1]));
}

__device__ __forceinline__ uint32_t round2h(float x, float y) {
    __half2 h = __floats2half2_rn(x, y);
    return *(uint32_t*)&h;
}

// ---------------------------------------------------------------------------
// RoPE cos/sin table
// ---------------------------------------------------------------------------
__global__ void __launch_bounds__(256) rope_table_kernel(
    const int* __restrict__ pos, float2* __restrict__ tab)
{
    int idx = blockIdx.x * blockDim.x + threadIdx.x;   // < SS*HALF
    int s = idx >> 5, i = idx & (HALF - 1);
    float p = (float)pos[s];
    float inv_freq = exp2f(-(float)i * (LOG2_THETA / (float)HALF));
    float sn, cs;
    sincosf(p * inv_freq, &sn, &cs);
    tab[idx] = make_float2(cs, sn);
}

// ---------------------------------------------------------------------------
// fp32 -> fp16 round: single tensor, and 4-weight batch
// ---------------------------------------------------------------------------
__global__ void __launch_bounds__(256) round_h_kernel(
    const float* __restrict__ src, __half* __restrict__ dst, int n4)
{
    int i = blockIdx.x * blockDim.x + threadIdx.x;
    if (i >= n4) return;
    float4 v = ((const float4*)src)[i];
    ((uint32_t*)dst)[i * 2 + 0] = round2h(v.x, v.y);
    ((uint32_t*)dst)[i * 2 + 1] = round2h(v.z, v.w);
}

__global__ void __launch_bounds__(256) round4_h_kernel(
    const float* __restrict__ w0, const float* __restrict__ w1,
    const float* __restrict__ w2, const float* __restrict__ w3,
    __half* __restrict__ outB, int n4)
{
    int i = blockIdx.x * blockDim.x + threadIdx.x;
    if (i >= n4) return;
    const int zz = blockIdx.y;
    const float* src = (zz == 0) ? w0 : (zz == 1) ? w1 : (zz == 2) ? w2 : w3;
    __half* dst = outB + (size_t)zz * D_MODEL * D_MODEL;
    float4 v = ((const float4*)src)[i];
    ((uint32_t*)dst)[i * 2 + 0] = round2h(v.x, v.y);
    ((uint32_t*)dst)[i * 2 + 1] = round2h(v.z, v.w);
}

// ---------------------------------------------------------------------------
// fp16 mma.sync GEMM (NT): C[M,N] = A[M,K] * B[N,K]^T, single fp16 operands.
// 128x128 tile, BK=16, 256 threads (8 warps, 2x4), warp tile 64x32.
// 4-stage cp.async (8KB/stage), single sync per k-step. 1 MMA per (i,j).
// FUSED=1 (QKV): z=0 -> rope+round Q; z=1 -> rope+round K; z=2 -> fp32 V.
// FUSED=0 (O-proj): plain fp32 epilogue.
// ---------------------------------------------------------------------------
#define GSTG 2048   // u32 per stage (A 4KB | B 4KB)

__device__ __forceinline__ void load_stage2(
    const __half* __restrict__ gA, const __half* __restrict__ gB,
    int Kdim, int k0, uint32_t* sb, int tid)
{
    const int m = tid >> 1;
    const int q = tid & 1;
    const size_t src = (size_t)m * Kdim + k0 + q * 8;
    const int aw = ((((m >> 4) * 4 + ((m >> 3) & 1) + 2 * q)) << 5) + (m & 7) * 4;
    const int bw = ((((m >> 3) * 2 + q)) << 5) + (m & 7) * 4;
    CP_ASYNC16(smem_u32(sb + aw),        gA + src);
    CP_ASYNC16(smem_u32(sb + 1024 + bw), gB + src);
}

template <int FUSED>
__global__ void __launch_bounds__(256) gemm_fp16_nt(
    const __half* __restrict__ A, const __half* __restrict__ WB,
    float* __restrict__ Cf,
    __half* __restrict__ qf, __half* __restrict__ kf,
    const float2* __restrict__ rope,
    int Mdim, int Ndim, int Kdim)
{
    extern __shared__ uint32_t smem4[];   // 4 stages x 2048 u32 = 32KB

    const int tid  = threadIdx.x;
    const int lane = tid & 31;
    const int warp = tid >> 5;
    const int wy   = warp >> 2;
    const int wx   = warp & 3;
    const int row0 = blockIdx.y * 128;
    const int col0 = blockIdx.x * 128;
    const int z    = blockIdx.z;
    const size_t zw = (size_t)z * D_MODEL * D_MODEL;

    const __half* gA = A + (size_t)row0 * Kdim;
    const __half* gB = WB + zw + (size_t)col0 * Kdim;

    float c[4][4][4];
#pragma unroll
    for (int i = 0; i < 4; ++i)
#pragma unroll
        for (int j = 0; j < 4; ++j)
#pragma unroll
            for (int r = 0; r < 4; ++r) c[i][j][r] = 0.f;

    const int NT = Kdim / 16;             // 64
    load_stage2(gA, gB, Kdim, 0,  smem4,            tid); CP_COMMIT();
    load_stage2(gA, gB, Kdim, 16, smem4 + GSTG,     tid); CP_COMMIT();
    load_stage2(gA, gB, Kdim, 32, smem4 + 2 * GSTG, tid); CP_COMMIT();

    for (int t = 0; t < NT; ++t) {
        if (t < NT - 2)      { CP_WAIT2(); }
        else if (t < NT - 1) { CP_WAIT1(); }
        else                 { CP_WAIT0(); }
        __syncthreads();   // data visibility + WAR guard for the issue below

        if (t + 3 < NT) {
            load_stage2(gA, gB, Kdim, (t + 3) * 16,
                        smem4 + ((t + 3) & 3) * GSTG, tid);
            CP_COMMIT();
        }

        const uint32_t* sb = smem4 + (t & 3) * GSTG;
        const uint32_t* pA = sb;
        const uint32_t* pB = sb + 1024;

        uint32_t a[4][4], b[4][2];
#pragma unroll
        for (int i = 0; i < 4; ++i) {
            const int base = (((wy * 4 + i) * 4) << 5) + lane;
#pragma unroll
            for (int r = 0; r < 4; ++r) a[i][r] = pA[base + (r << 5)];
        }
#pragma unroll
        for (int j = 0; j < 4; ++j) {
            const int base = (((wx * 4 + j) * 2) << 5) + lane;
#pragma unroll
            for (int r = 0; r < 2; ++r) b[j][r] = pB[base + (r << 5)];
        }

#pragma unroll
        for (int i = 0; i < 4; ++i)
#pragma unroll
            for (int j = 0; j < 4; ++j)
                mma_fp16(c[i][j], a[i], b[j]);
    }

    const int r  = lane >> 2;
    const int cc = (lane & 3) * 2;

    if (FUSED && z < 2) {
        __half* of = z ? kf : qf;
#pragma unroll
        for (int i = 0; i < 4; ++i)
#pragma unroll
            for (int j = 0; j < 4; ++j) {
                const int col = col0 + wx * 32 + j * 8 + cc;       // even
                const int pi  = (col & 63) >> 1;                   // rope pair idx
                const int m0r = row0 + wy * 64 + i * 16 + r;
                const int m1r = m0r + 8;
                float2 t0 = rope[(size_t)(m0r & (SS - 1)) * HALF + pi];
                float2 t1 = rope[(size_t)(m1r & (SS - 1)) * HALF + pi];
                float re0 = c[i][j][0] * t0.x - c[i][j][1] * t0.y;
                float ro0 = c[i][j][0] * t0.y + c[i][j][1] * t0.x;
                float re1 = c[i][j][2] * t1.x - c[i][j][3] * t1.y;
                float ro1 = c[i][j][2] * t1.y + c[i][j][3] * t1.x;
                *(uint32_t*)(of + (size_t)m0r * D_MODEL + col) = round2h(re0, ro0);
                *(uint32_t*)(of + (size_t)m1r * D_MODEL + col) = round2h(re1, ro1);
            }
    } else {
#pragma unroll
        for (int i = 0; i < 4; ++i)
#pragma unroll
            for (int j = 0; j < 4; ++j) {
                float* cp = Cf + (size_t)(row0 + wy * 64 + i * 16 + r) * Ndim
                              + col0 + wx * 32 + j * 8 + cc;
                *(float2*)cp = make_float2(c[i][j][0], c[i][j][1]);
                *(float2*)(cp + 8 * (size_t)Ndim) = make_float2(c[i][j][2], c[i][j][3]);
            }
    }
}

// ---------------------------------------------------------------------------
// V transpose + round: fp32 [b*S+t][1024] -> vtf fp16 [(b*16+h)*64+d][S]
// ---------------------------------------------------------------------------
__global__ void __launch_bounds__(256) vtrans_round_kernel(
    const float* __restrict__ v, __half* __restrict__ vtf)
{
    __shared__ float tile[64][65];
    const int tb = blockIdx.x;
    const int bh = blockIdx.y;
    const int b  = bh >> 4, h = bh & 15;
    const int tid = threadIdx.x;

#pragma unroll
    for (int i = 0; i < 4; ++i) {
        int e = tid + i * 256;
        int t = e >> 4;
        int d4 = (e & 15) * 4;
        float4 vv = *(const float4*)(v + (size_t)(b * SS + tb * 64 + t) * D_MODEL
                                       + h * DK + d4);
        tile[d4 + 0][t] = vv.x;
        tile[d4 + 1][t] = vv.y;
        tile[d4 + 2][t] = vv.z;
        tile[d4 + 3][t] = vv.w;
    }
    __syncthreads();

#pragma unroll
    for (int i = 0; i < 8; ++i) {
        int e = tid + i * 256;
        int d = e >> 5;
        int t2 = (e & 31) * 2;
        size_t dst = ((size_t)(bh * 64 + d)) * SS + tb * 64 + t2;
        *(uint32_t*)(vtf + dst) = round2h(tile[d][t2], tile[d][t2 + 1]);
    }
}

// ---------------------------------------------------------------------------
// Tensor-core flash attention (causal), single fp16 everywhere.
// 1 MMA per QK fragment, 1 per PV fragment. fp32 softmax/accumulators.
// Smem: 2 stages x 16KB (K 8KB | V 8KB) + Q 16KB = 48KB.
// ---------------------------------------------------------------------------
__device__ __forceinline__ void attn_load_tile(
    uint32_t* dsm, int nsb, int tid, int b, int kt, int hoff, size_t vrow0,
    const __half* __restrict__ Kf, const __half* __restrict__ Vtf)
{
#pragma unroll
    for (int i = 0; i < 4; ++i) {
        int c = tid + i * 256;
        if (c < 512) {
            int t = c >> 3, kq = c & 7;
            int wd = ((((t >> 3) * 4 + (kq >> 1)) * 2 + (kq & 1)) << 5) + (t & 7) * 4;
            const __half* src = Kf
                + (size_t)(b * SS + kt * 64 + t) * D_MODEL + hoff + kq * 8;
            CP_ASYNC16(smem_u32(dsm + nsb + wd), src);
        } else {
            int c2 = c - 512;
            int d = c2 >> 3, tq = c2 & 7;
            int wd = ((((d >> 3) * 4 + (tq >> 1)) * 2 + (tq & 1)) << 5) + (d & 7) * 4;
            const __half* src = Vtf + vrow0 + (size_t)d * SS + kt * 64 + tq * 8;
            CP_ASYNC16(smem_u32(dsm + nsb + 2048 + wd), src);
        }
    }
}

__global__ void __launch_bounds__(256) attn_tc_kernel(
    const __half* __restrict__ Qf, const __half* __restrict__ Kf,
    const __half* __restrict__ Vtf, __half* __restrict__ Af)
{
    extern __shared__ uint32_t dsm[];   // 12288 u32 = 48KB

    const int qi  = (gridDim.x - 1) - blockIdx.x;   // big work first (LPT)
    const int h   = blockIdx.y;
    const int b   = blockIdx.z;
    const int tid = threadIdx.x;
    const int lane = tid & 31;
    const int w    = tid >> 5;

    const int tok0 = b * SS + qi * 128;
    const int hoff = h * DK;
    const size_t vrow0 = (size_t)((b * 16 + h) * 64) * SS;
    const int kt_last = qi * 2 + 1;

    // prologue: Q into 8192.. region (16KB), tile0 into stage0
#pragma unroll
    for (int i = 0; i < 4; ++i) {
        int c = tid + i * 256;                // 0..1023
        int m = c >> 3, kq = c & 7;
        int wd = ((((m >> 4) * 4 + (kq >> 1)) * 4 + ((m >> 3) & 1) + 2 * (kq & 1)) << 5)
                 + (m & 7) * 4;
        const __half* src = Qf + (size_t)(tok0 + m) * D_MODEL + hoff + kq * 8;
        CP_ASYNC16(smem_u32(dsm + 8192 + wd), src);
    }
    attn_load_tile(dsm, 0, tid, b, 0, hoff, vrow0, Kf, Vtf);
    CP_COMMIT();
    CP_WAIT0();
    __syncthreads();

    uint32_t qf[4][4];
#pragma unroll
    for (int ks = 0; ks < 4; ++ks)
#pragma unroll
        for (int r = 0; r < 4; ++r) {
            int wd = (((w * 4 + ks) * 4 + r) << 5) + lane;
            qf[ks][r] = dsm[8192 + wd];
        }
    __syncthreads();

    float acc[8][4];
#pragma unroll
    for (int j = 0; j < 8; ++j)
#pragma unroll
        for (int r = 0; r < 4; ++r) acc[j][r] = 0.f;
    float m0 = -1e30f, m1 = -1e30f, l0 = 0.f, l1 = 0.f;

    const int q0w = qi * 128 + w * 16;

    for (int kt = 0; kt <= kt_last; ++kt) {
        const int sb = (kt & 1) * 4096;
        CP_WAIT0();        // loads for kt complete
        __syncthreads();   // visibility + WAR guard for the issue below

        if (kt < kt_last) {
            attn_load_tile(dsm, ((kt + 1) & 1) * 4096, tid, b, kt + 1,
                           hoff, vrow0, Kf, Vtf);
            CP_COMMIT();
        }

        if (kt * 64 <= q0w + 15) {
            const uint32_t* sK = dsm + sb;
            const uint32_t* sV = dsm + sb + 2048;

            float s[8][4];
#pragma unroll
            for (int j = 0; j < 8; ++j)
#pragma unroll
                for (int r = 0; r < 4; ++r) s[j][r] = 0.f;

#pragma unroll
            for (int ks = 0; ks < 4; ++ks)
#pragma unroll
                for (int jn = 0; jn < 8; ++jn) {
                    int base = ((jn * 4 + ks) << 6) + lane;
                    uint32_t bf[2] = {sK[base], sK[base + 32]};
                    mma_fp16(s[jn], qf[ks], bf);
                }

#pragma unroll
            for (int j = 0; j < 8; ++j)
#pragma unroll
                for (int r = 0; r < 4; ++r) s[j][r] *= 0.125f;

            if (kt * 64 + 63 > q0w) {
                const int row0g = q0w + (lane >> 2);
                const int colbg = kt * 64 + 2 * (lane & 3);
#pragma unroll
                for (int jn = 0; jn < 8; ++jn) {
                    int c0 = colbg + jn * 8;
                    if (c0 > row0g)     s[jn][0] = -1e30f;
                    if (c0 + 1 > row0g) s[jn][1] = -1e30f;
                    if (c0 > row0g + 8)     s[jn][2] = -1e30f;
                    if (c0 + 1 > row0g + 8) s[jn][3] = -1e30f;
                }
            }

            float mx0 = -1e30f, mx1 = -1e30f;
#pragma unroll
            for (int j = 0; j < 8; ++j) {
                mx0 = fmaxf(mx0, fmaxf(s[j][0], s[j][1]));
                mx1 = fmaxf(mx1, fmaxf(s[j][2], s[j][3]));
            }
            mx0 = fmaxf(mx0, __shfl_xor_sync(0xffffffffu, mx0, 1));
            mx0 = fmaxf(mx0, __shfl_xor_sync(0xffffffffu, mx0, 2));
            mx1 = fmaxf(mx1, __shfl_xor_sync(0xffffffffu, mx1, 1));
            mx1 = fmaxf(mx1, __shfl_xor_sync(0xffffffffu, mx1, 2));

            float mn0 = fmaxf(m0, mx0), mn1 = fmaxf(m1, mx1);
            float al0 = __expf(m0 - mn0), al1 = __expf(m1 - mn1);
            m0 = mn0; m1 = mn1;

            float sum0 = 0.f, sum1 = 0.f;
#pragma unroll
            for (int j = 0; j < 8; ++j) {
                s[j][0] = __expf(s[j][0] - mn0);
                s[j][1] = __expf(s[j][1] - mn0);
                s[j][2] = __expf(s[j][2] - mn1);
                s[j][3] = __expf(s[j][3] - mn1);
                sum0 += s[j][0] + s[j][1];
                sum1 += s[j][2] + s[j][3];
            }
            sum0 += __shfl_xor_sync(0xffffffffu, sum0, 1);
            sum0 += __shfl_xor_sync(0xffffffffu, sum0, 2);
            sum1 += __shfl_xor_sync(0xffffffffu, sum1, 1);
            sum1 += __shfl_xor_sync(0xffffffffu, sum1, 2);
            l0 = l0 * al0 + sum0;
            l1 = l1 * al1 + sum1;

#pragma unroll
            for (int j = 0; j < 8; ++j) {
                acc[j][0] *= al0; acc[j][1] *= al0;
                acc[j][2] *= al1; acc[j][3] *= al1;
            }

            // P rounded to single fp16; 1 MMA per (kk, jd)
#pragma unroll
            for (int kk = 0; kk < 4; ++kk) {
                uint32_t pf4[4];
                pf4[0] = round2h(s[2 * kk][0],     s[2 * kk][1]);
                pf4[1] = round2h(s[2 * kk][2],     s[2 * kk][3]);
                pf4[2] = round2h(s[2 * kk + 1][0], s[2 * kk + 1][1]);
                pf4[3] = round2h(s[2 * kk + 1][2], s[2 * kk + 1][3]);
#pragma unroll
                for (int jd = 0; jd < 8; ++jd) {
                    int base = ((jd * 4 + kk) << 6) + lane;
                    uint32_t vf[2] = {sV[base], sV[base + 32]};
                    mma_fp16(acc[jd], pf4, vf);
                }
            }
        }
        // no trailing sync: next iteration's leading sync is the WAR guard
    }

    // epilogue: normalize + round to fp16 (input of O-projection)
    const float inv0 = 1.f / l0, inv1 = 1.f / l1;
    const int r  = lane >> 2;
    const int cc = 2 * (lane & 3);
    const size_t r0 = (size_t)(tok0 + w * 16 + r) * D_MODEL + hoff;
    const size_t r1 = r0 + 8 * (size_t)D_MODEL;
#pragma unroll
    for (int jd = 0; jd < 8; ++jd) {
        *(uint32_t*)(Af + r0 + jd * 8 + cc) = round2h(acc[jd][0] * inv0, acc[jd][1] * inv0);
        *(uint32_t*)(Af + r1 + jd * 8 + cc) = round2h(acc[jd][2] * inv1, acc[jd][3] * inv1);
    }
}

// ---------------------------------------------------------------------------
extern "C" void kernel_launch(void* const* d_in, const int* in_sizes, int n_in,
                              void* d_out, int out_size)
{
    const float* wq  = (const float*)d_in[0];
    const float* wk  = (const float*)d_in[1];
    const float* wv  = (const float*)d_in[2];
    const float* wo  = (const float*)d_in[3];
    const float* x   = (const float*)d_in[4];
    const int*   pos = (const int*)d_in[5];
    float* out = (float*)d_out;

    float* dv;
    cudaGetSymbolAddress((void**)&dv, g_v);
    __half *xf, *af, *wf, *qf, *kf, *vtf;
    float2* ropet;
    cudaGetSymbolAddress((void**)&xf,  g_xf);
    cudaGetSymbolAddress((void**)&af,  g_af);
    cudaGetSymbolAddress((void**)&wf,  g_wf);
    cudaGetSymbolAddress((void**)&qf,  g_qf);
    cudaGetSymbolAddress((void**)&kf,  g_kf);
    cudaGetSymbolAddress((void**)&vtf, g_vtf);
    cudaGetSymbolAddress((void**)&ropet, g_rope);

    const size_t WSZ = (size_t)D_MODEL * D_MODEL;
    const int n4x = (int)((size_t)MM * D_MODEL / 4);
    const int n4w = (int)(WSZ / 4);

    rope_table_kernel<<<(SS * HALF) / 256, 256>>>(pos, ropet);
    round_h_kernel<<<(n4x + 255) / 256, 256>>>(x, xf, n4x);
    round4_h_kernel<<<dim3((n4w + 255) / 256, 4), 256>>>(wq, wk, wv, wo, wf, n4w);

    cudaFuncSetAttribute(gemm_fp16_nt<1>,
                         cudaFuncAttributeMaxDynamicSharedMemorySize, 4 * GSTG * 4);
    cudaFuncSetAttribute(gemm_fp16_nt<0>,
                         cudaFuncAttributeMaxDynamicSharedMemorySize, 4 * GSTG * 4);

    // fused QKV: z=0 -> rope-round Q, z=1 -> rope-round K, z=2 -> fp32 V
    gemm_fp16_nt<1><<<dim3(D_MODEL / 128, MM / 128, 3), 256, 4 * GSTG * 4>>>(
        xf, wf, dv, qf, kf, ropet, MM, D_MODEL, D_MODEL);

    vtrans_round_kernel<<<dim3(SS / 64, BB * NUM_HEADS), 256>>>(dv, vtf);

    cudaFuncSetAttribute(attn_tc_kernel,
                         cudaFuncAttributeMaxDynamicSharedMemorySize, 49152);
    attn_tc_kernel<<<dim3(SS / 128, NUM_HEADS, BB), 256, 49152>>>(
        qf, kf, vtf, af);

    // O projection: plain fp32 epilogue, weight slot 3
    gemm_fp16_nt<0><<<dim3(D_MODEL / 128, MM / 128, 1), 256, 4 * GSTG * 4>>>(
        af, wf + 3 * WSZ, out, nullptr, nullptr, ropet, MM, D_MODEL, D_MODEL);
}

// round 15
// speedup vs baseline: 2.0849x; 1.0189x over previous
#include <cuda_runtime.h>
#include <cuda_fp16.h>
#include <math.h>
#include <stdint.h>

#define D_MODEL 1024
#define NUM_HEADS 16
#define DK 64
#define HALF 32
#define BB 4
#define SS 2048
#define MM (BB * SS)           // 8192 tokens
#define LOG2_THETA 13.287712379549449f   // log2(10000)

// ---------------- scratch (device globals: no allocation allowed) ----------
__device__ float g_v[(size_t)MM * D_MODEL];            // V projection (fp32)

__device__ __half g_xf[(size_t)MM * D_MODEL];          // x fp16
__device__ __half g_af[(size_t)MM * D_MODEL];          // attention out fp16
__device__ __half g_wf[4][(size_t)D_MODEL * D_MODEL];  // weights fp16

__device__ __half g_qf[(size_t)MM * D_MODEL];          // Q (roped, pre-scaled) fp16
__device__ __half g_kf[(size_t)MM * D_MODEL];          // K (roped) fp16
__device__ __half g_vtf[(size_t)MM * D_MODEL];         // V^T fp16

__device__ float2 g_rope[(size_t)SS * HALF];           // {cos, sin} table

// ---------------------------------------------------------------------------
__device__ __forceinline__ uint32_t smem_u32(const void* p) {
    return (uint32_t)__cvta_generic_to_shared(p);
}
#define CP_ASYNC16(dst, src) \
    asm volatile("cp.async.cg.shared.global [%0], [%1], 16;\n" :: "r"(dst), "l"(src))
#define CP_COMMIT() asm volatile("cp.async.commit_group;\n" ::: "memory")
#define CP_WAIT2()  asm volatile("cp.async.wait_group 2;\n" ::: "memory")
#define CP_WAIT1()  asm volatile("cp.async.wait_group 1;\n" ::: "memory")
#define CP_WAIT0()  asm volatile("cp.async.wait_group 0;\n" ::: "memory")

__device__ __forceinline__ void mma_fp16(float c[4], const uint32_t a[4],
                                         const uint32_t b[2]) {
    asm volatile(
        "mma.sync.aligned.m16n8k16.row.col.f32.f16.f16.f32 "
        "{%0,%1,%2,%3}, {%4,%5,%6,%7}, {%8,%9}, {%0,%1,%2,%3};\n"
        : "+f"(c[0]), "+f"(c[1]), "+f"(c[2]), "+f"(c[3])
        : "r"(a[0]), "r"(a[1]), "r"(a[2]), "r"(a[3]), "r"(b[0]), "r"(b[1]));
}

__device__ __forceinline__ uint32_t round2h(float x, float y) {
    __half2 h = __floats2half2_rn(x, y);
    return *(uint32_t*)&h;
}

// ---------------------------------------------------------------------------
// RoPE cos/sin table
// ---------------------------------------------------------------------------
__global__ void __launch_bounds__(256) rope_table_kernel(
    const int* __restrict__ pos, float2* __restrict__ tab)
{
    int idx = blockIdx.x * blockDim.x + threadIdx.x;   // < SS*HALF
    int s = idx >> 5, i = idx & (HALF - 1);
    float p = (float)pos[s];
    float inv_freq = exp2f(-(float)i * (LOG2_THETA / (float)HALF));
    float sn, cs;
    sincosf(p * inv_freq, &sn, &cs);
    tab[idx] = make_float2(cs, sn);
}

// ---------------------------------------------------------------------------
// fp32 -> fp16 round: single tensor, and 4-weight batch
// ---------------------------------------------------------------------------
__global__ void __launch_bounds__(256) round_h_kernel(
    const float* __restrict__ src, __half* __restrict__ dst, int n4)
{
    int i = blockIdx.x * blockDim.x + threadIdx.x;
    if (i >= n4) return;
    float4 v = ((const float4*)src)[i];
    ((uint32_t*)dst)[i * 2 + 0] = round2h(v.x, v.y);
    ((uint32_t*)dst)[i * 2 + 1] = round2h(v.z, v.w);
}

__global__ void __launch_bounds__(256) round4_h_kernel(
    const float* __restrict__ w0, const float* __restrict__ w1,
    const float* __restrict__ w2, const float* __restrict__ w3,
    __half* __restrict__ outB, int n4)
{
    int i = blockIdx.x * blockDim.x + threadIdx.x;
    if (i >= n4) return;
    const int zz = blockIdx.y;
    const float* src = (zz == 0) ? w0 : (zz == 1) ? w1 : (zz == 2) ? w2 : w3;
    __half* dst = outB + (size_t)zz * D_MODEL * D_MODEL;
    float4 v = ((const float4*)src)[i];
    ((uint32_t*)dst)[i * 2 + 0] = round2h(v.x, v.y);
    ((uint32_t*)dst)[i * 2 + 1] = round2h(v.z, v.w);
}

// ---------------------------------------------------------------------------
// fp16 mma.sync GEMM (NT), BK=32 per sync (2 k16 slabs/stage).
// 128x128 tile, 256 threads (8 warps, 2x4), warp tile 64x32.
// 4 stages x 16KB = 64KB, single sync per BK=32 step (32 syncs total).
// FUSED=1 (QKV): z=0 -> rope+scale+round Q; z=1 -> rope+round K; z=2 -> fp32 V.
// FUSED=0 (O-proj): plain fp32 epilogue.
// ---------------------------------------------------------------------------
#define GSTG 4096   // u32 per stage: A slab0|A slab1|B slab0|B slab1, 4KB each

__device__ __forceinline__ void load_stage32(
    const __half* __restrict__ gA, const __half* __restrict__ gB,
    int Kdim, int k0, uint32_t* sb, int tid)
{
    const int m = tid >> 1;
    const int q = tid & 1;
    const int aw = ((((m >> 4) * 4 + ((m >> 3) & 1) + 2 * q)) << 5) + (m & 7) * 4;
    const int bw = ((((m >> 3) * 2 + q)) << 5) + (m & 7) * 4;
#pragma unroll
    for (int slab = 0; slab < 2; ++slab) {
        const size_t src = (size_t)m * Kdim + k0 + slab * 16 + q * 8;
        CP_ASYNC16(smem_u32(sb + slab * 1024 + aw),        gA + src);
        CP_ASYNC16(smem_u32(sb + 2048 + slab * 1024 + bw), gB + src);
    }
}

template <int FUSED>
__global__ void __launch_bounds__(256) gemm_fp16_nt(
    const __half* __restrict__ A, const __half* __restrict__ WB,
    float* __restrict__ Cf,
    __half* __restrict__ qf, __half* __restrict__ kf,
    const float2* __restrict__ rope,
    int Mdim, int Ndim, int Kdim)
{
    extern __shared__ uint32_t smem4[];   // 4 stages x 4096 u32 = 64KB

    const int tid  = threadIdx.x;
    const int lane = tid & 31;
    const int warp = tid >> 5;
    const int wy   = warp >> 2;
    const int wx   = warp & 3;
    const int row0 = blockIdx.y * 128;
    const int col0 = blockIdx.x * 128;
    const int z    = blockIdx.z;
    const size_t zw = (size_t)z * D_MODEL * D_MODEL;

    const __half* gA = A + (size_t)row0 * Kdim;
    const __half* gB = WB + zw + (size_t)col0 * Kdim;

    float c[4][4][4];
#pragma unroll
    for (int i = 0; i < 4; ++i)
#pragma unroll
        for (int j = 0; j < 4; ++j)
#pragma unroll
            for (int r = 0; r < 4; ++r) c[i][j][r] = 0.f;

    const int NT2 = Kdim / 32;            // 32
    load_stage32(gA, gB, Kdim, 0,  smem4,            tid); CP_COMMIT();
    load_stage32(gA, gB, Kdim, 32, smem4 + GSTG,     tid); CP_COMMIT();
    load_stage32(gA, gB, Kdim, 64, smem4 + 2 * GSTG, tid); CP_COMMIT();

    for (int t = 0; t < NT2; ++t) {
        if (t < NT2 - 2)      { CP_WAIT2(); }
        else if (t < NT2 - 1) { CP_WAIT1(); }
        else                  { CP_WAIT0(); }
        __syncthreads();   // data visibility + WAR guard for the issue below

        if (t + 3 < NT2) {
            load_stage32(gA, gB, Kdim, (t + 3) * 32,
                         smem4 + ((t + 3) & 3) * GSTG, tid);
            CP_COMMIT();
        }

        const uint32_t* sb = smem4 + (t & 3) * GSTG;
#pragma unroll
        for (int ks = 0; ks < 2; ++ks) {
            const uint32_t* pA = sb + ks * 1024;
            const uint32_t* pB = sb + 2048 + ks * 1024;

            uint32_t a[4][4], b[4][2];
#pragma unroll
            for (int i = 0; i < 4; ++i) {
                const int base = (((wy * 4 + i) * 4) << 5) + lane;
#pragma unroll
                for (int r = 0; r < 4; ++r) a[i][r] = pA[base + (r << 5)];
            }
#pragma unroll
            for (int j = 0; j < 4; ++j) {
                const int base = (((wx * 4 + j) * 2) << 5) + lane;
#pragma unroll
                for (int r = 0; r < 2; ++r) b[j][r] = pB[base + (r << 5)];
            }

#pragma unroll
            for (int i = 0; i < 4; ++i)
#pragma unroll
                for (int j = 0; j < 4; ++j)
                    mma_fp16(c[i][j], a[i], b[j]);
        }
    }

    const int r  = lane >> 2;
    const int cc = (lane & 3) * 2;

    if (FUSED && z < 2) {
        __half* of = z ? kf : qf;
        const float sc = z ? 1.0f : 0.125f;   // fold 1/sqrt(dk) into Q (2^-3 exact)
#pragma unroll
        for (int i = 0; i < 4; ++i)
#pragma unroll
            for (int j = 0; j < 4; ++j) {
                const int col = col0 + wx * 32 + j * 8 + cc;       // even
                const int pi  = (col & 63) >> 1;                   // rope pair idx
                const int m0r = row0 + wy * 64 + i * 16 + r;
                const int m1r = m0r + 8;
                float2 t0 = rope[(size_t)(m0r & (SS - 1)) * HALF + pi];
                float2 t1 = rope[(size_t)(m1r & (SS - 1)) * HALF + pi];
                float re0 = (c[i][j][0] * t0.x - c[i][j][1] * t0.y) * sc;
                float ro0 = (c[i][j][0] * t0.y + c[i][j][1] * t0.x) * sc;
                float re1 = (c[i][j][2] * t1.x - c[i][j][3] * t1.y) * sc;
                float ro1 = (c[i][j][2] * t1.y + c[i][j][3] * t1.x) * sc;
                *(uint32_t*)(of + (size_t)m0r * D_MODEL + col) = round2h(re0, ro0);
                *(uint32_t*)(of + (size_t)m1r * D_MODEL + col) = round2h(re1, ro1);
            }
    } else {
#pragma unroll
        for (int i = 0; i < 4; ++i)
#pragma unroll
            for (int j = 0; j < 4; ++j) {
                float* cp = Cf + (size_t)(row0 + wy * 64 + i * 16 + r) * Ndim
                              + col0 + wx * 32 + j * 8 + cc;
                *(float2*)cp = make_float2(c[i][j][0], c[i][j][1]);
                *(float2*)(cp + 8 * (size_t)Ndim) = make_float2(c[i][j][2], c[i][j][3]);
            }
    }
}

// ---------------------------------------------------------------------------
// V transpose + round: fp32 [b*S+t][1024] -> vtf fp16 [(b*16+h)*64+d][S]
// ---------------------------------------------------------------------------
__global__ void __launch_bounds__(256) vtrans_round_kernel(
    const float* __restrict__ v, __half* __restrict__ vtf)
{
    __shared__ float tile[64][65];
    const int tb = blockIdx.x;
    const int bh = blockIdx.y;
    const int b  = bh >> 4, h = bh & 15;
    const int tid = threadIdx.x;

#pragma unroll
    for (int i = 0; i < 4; ++i) {
        int e = tid + i * 256;
        int t = e >> 4;
        int d4 = (e & 15) * 4;
        float4 vv = *(const float4*)(v + (size_t)(b * SS + tb * 64 + t) * D_MODEL
                                       + h * DK + d4);
        tile[d4 + 0][t] = vv.x;
        tile[d4 + 1][t] = vv.y;
        tile[d4 + 2][t] = vv.z;
        tile[d4 + 3][t] = vv.w;
    }
    __syncthreads();

#pragma unroll
    for (int i = 0; i < 8; ++i) {
        int e = tid + i * 256;
        int d = e >> 5;
        int t2 = (e & 31) * 2;
        size_t dst = ((size_t)(bh * 64 + d)) * SS + tb * 64 + t2;
        *(uint32_t*)(vtf + dst) = round2h(tile[d][t2], tile[d][t2 + 1]);
    }
}

// ---------------------------------------------------------------------------
// Tensor-core flash attention (causal), single fp16, 2 CTAs/SM.
// Q pre-scaled by 1/sqrt(dk) -> no scale multiply in the inner loop.
// Smem: 2 stages x 16KB (K 8KB | V 8KB) + Q 16KB = 48KB.
// ---------------------------------------------------------------------------
__device__ __forceinline__ void attn_load_tile(
    uint32_t* dsm, int nsb, int tid, int b, int kt, int hoff, size_t vrow0,
    const __half* __restrict__ Kf, const __half* __restrict__ Vtf)
{
#pragma unroll
    for (int i = 0; i < 4; ++i) {
        int c = tid + i * 256;
        if (c < 512) {
            int t = c >> 3, kq = c & 7;
            int wd = ((((t >> 3) * 4 + (kq >> 1)) * 2 + (kq & 1)) << 5) + (t & 7) * 4;
            const __half* src = Kf
                + (size_t)(b * SS + kt * 64 + t) * D_MODEL + hoff + kq * 8;
            CP_ASYNC16(smem_u32(dsm + nsb + wd), src);
        } else {
            int c2 = c - 512;
            int d = c2 >> 3, tq = c2 & 7;
            int wd = ((((d >> 3) * 4 + (tq >> 1)) * 2 + (tq & 1)) << 5) + (d & 7) * 4;
            const __half* src = Vtf + vrow0 + (size_t)d * SS + kt * 64 + tq * 8;
            CP_ASYNC16(smem_u32(dsm + nsb + 2048 + wd), src);
        }
    }
}

__global__ void __launch_bounds__(256, 2) attn_tc_kernel(
    const __half* __restrict__ Qf, const __half* __restrict__ Kf,
    const __half* __restrict__ Vtf, __half* __restrict__ Af)
{
    extern __shared__ uint32_t dsm[];   // 12288 u32 = 48KB

    const int qi  = (gridDim.x - 1) - blockIdx.x;   // big work first (LPT)
    const int h   = blockIdx.y;
    const int b   = blockIdx.z;
    const int tid = threadIdx.x;
    const int lane = tid & 31;
    const int w    = tid >> 5;

    const int tok0 = b * SS + qi * 128;
    const int hoff = h * DK;
    const size_t vrow0 = (size_t)((b * 16 + h) * 64) * SS;
    const int kt_last = qi * 2 + 1;

    // prologue: Q into 8192.. region (16KB), tile0 into stage0
#pragma unroll
    for (int i = 0; i < 4; ++i) {
        int c = tid + i * 256;                // 0..1023
        int m = c >> 3, kq = c & 7;
        int wd = ((((m >> 4) * 4 + (kq >> 1)) * 4 + ((m >> 3) & 1) + 2 * (kq & 1)) << 5)
                 + (m & 7) * 4;
        const __half* src = Qf + (size_t)(tok0 + m) * D_MODEL + hoff + kq * 8;
        CP_ASYNC16(smem_u32(dsm + 8192 + wd), src);
    }
    attn_load_tile(dsm, 0, tid, b, 0, hoff, vrow0, Kf, Vtf);
    CP_COMMIT();
    CP_WAIT0();
    __syncthreads();

    uint32_t qf[4][4];
#pragma unroll
    for (int ks = 0; ks < 4; ++ks)
#pragma unroll
        for (int r = 0; r < 4; ++r) {
            int wd = (((w * 4 + ks) * 4 + r) << 5) + lane;
            qf[ks][r] = dsm[8192 + wd];
        }
    __syncthreads();

    float acc[8][4];
#pragma unroll
    for (int j = 0; j < 8; ++j)
#pragma unroll
        for (int r = 0; r < 4; ++r) acc[j][r] = 0.f;
    float m0 = -1e30f, m1 = -1e30f, l0 = 0.f, l1 = 0.f;

    const int q0w = qi * 128 + w * 16;

    for (int kt = 0; kt <= kt_last; ++kt) {
        const int sb = (kt & 1) * 4096;
        CP_WAIT0();        // loads for kt complete
        __syncthreads();   // visibility + WAR guard for the issue below

        if (kt < kt_last) {
            attn_load_tile(dsm, ((kt + 1) & 1) * 4096, tid, b, kt + 1,
                           hoff, vrow0, Kf, Vtf);
            CP_COMMIT();
        }

        if (kt * 64 <= q0w + 15) {
            const uint32_t* sK = dsm + sb;
            const uint32_t* sV = dsm + sb + 2048;

            float s[8][4];
#pragma unroll
            for (int j = 0; j < 8; ++j)
#pragma unroll
                for (int r = 0; r < 4; ++r) s[j][r] = 0.f;

#pragma unroll
            for (int ks = 0; ks < 4; ++ks)
#pragma unroll
                for (int jn = 0; jn < 8; ++jn) {
                    int base = ((jn * 4 + ks) << 6) + lane;
                    uint32_t bf[2] = {sK[base], sK[base + 32]};
                    mma_fp16(s[jn], qf[ks], bf);
                }

            if (kt * 64 + 63 > q0w) {
                const int row0g = q0w + (lane >> 2);
                const int colbg = kt * 64 + 2 * (lane & 3);
#pragma unroll
                for (int jn = 0; jn < 8; ++jn) {
                    int c0 = colbg + jn * 8;
                    if (c0 > row0g)     s[jn][0] = -1e30f;
                    if (c0 + 1 > row0g) s[jn][1] = -1e30f;
                    if (c0 > row0g + 8)     s[jn][2] = -1e30f;
                    if (c0 + 1 > row0g + 8) s[jn][3] = -1e30f;
                }
            }

            float mx0 = -1e30f, mx1 = -1e30f;
#pragma unroll
            for (int j = 0; j < 8; ++j) {
                mx0 = fmaxf(mx0, fmaxf(s[j][0], s[j][1]));
                mx1 = fmaxf(mx1, fmaxf(s[j][2], s[j][3]));
            }
            mx0 = fmaxf(mx0, __shfl_xor_sync(0xffffffffu, mx0, 1));
            mx0 = fmaxf(mx0, __shfl_xor_sync(0xffffffffu, mx0, 2));
            mx1 = fmaxf(mx1, __shfl_xor_sync(0xffffffffu, mx1, 1));
            mx1 = fmaxf(mx1, __shfl_xor_sync(0xffffffffu, mx1, 2));

            float mn0 = fmaxf(m0, mx0), mn1 = fmaxf(m1, mx1);
            float al0 = __expf(m0 - mn0), al1 = __expf(m1 - mn1);
            m0 = mn0; m1 = mn1;

            float sum0 = 0.f, sum1 = 0.f;
#pragma unroll
            for (int j = 0; j < 8; ++j) {
                s[j][0] = __expf(s[j][0] - mn0);
                s[j][1] = __expf(s[j][1] - mn0);
                s[j][2] = __expf(s[j][2] - mn1);
                s[j][3] = __expf(s[j][3] - mn1);
                sum0 += s[j][0] + s[j][1];
                sum1 += s[j][2] + s[j][3];
            }
            sum0 += __shfl_xor_sync(0xffffffffu, sum0, 1);
            sum0 += __shfl_xor_sync(0xffffffffu, sum0, 2);
            sum1 += __shfl_xor_sync(0xffffffffu, sum1, 1);
            sum1 += __shfl_xor_sync(0xffffffffu, sum1, 2);
            l0 = l0 * al0 + sum0;
            l1 = l1 * al1 + sum1;

#pragma unroll
            for (int j = 0; j < 8; ++j) {
                acc[j][0] *= al0; acc[j][1] *= al0;
                acc[j][2] *= al1; acc[j][3] *= al1;
            }

            // P rounded to single fp16; 1 MMA per (kk, jd)
#pragma unroll
            for (int kk = 0; kk < 4; ++kk) {
                uint32_t pf4[4];
                pf4[0] = round2h(s[2 * kk][0],     s[2 * kk][1]);
                pf4[1] = round2h(s[2 * kk][2],     s[2 * kk][3]);
                pf4[2] = round2h(s[2 * kk + 1][0], s[2 * kk + 1][1]);
                pf4[3] = round2h(s[2 * kk + 1][2], s[2 * kk + 1][3]);
#pragma unroll
                for (int jd = 0; jd < 8; ++jd) {
                    int base = ((jd * 4 + kk) << 6) + lane;
                    uint32_t vf[2] = {sV[base], sV[base + 32]};
                    mma_fp16(acc[jd], pf4, vf);
                }
            }
        }
        // no trailing sync: next iteration's leading sync is the WAR guard
    }

    // epilogue: normalize + round to fp16 (input of O-projection)
    const float inv0 = 1.f / l0, inv1 = 1.f / l1;
    const int r  = lane >> 2;
    const int cc = 2 * (lane & 3);
    const size_t r0 = (size_t)(tok0 + w * 16 + r) * D_MODEL + hoff;
    const size_t r1 = r0 + 8 * (size_t)D_MODEL;
#pragma unroll
    for (int jd = 0; jd < 8; ++jd) {
        *(uint32_t*)(Af + r0 + jd * 8 + cc) = round2h(acc[jd][0] * inv0, acc[jd][1] * inv0);
        *(uint32_t*)(Af + r1 + jd * 8 + cc) = round2h(acc[jd][2] * inv1, acc[jd][3] * inv1);
    }
}

// ---------------------------------------------------------------------------
extern "C" void kernel_launch(void* const* d_in, const int* in_sizes, int n_in,
                              void* d_out, int out_size)
{
    const float* wq  = (const float*)d_in[0];
    const float* wk  = (const float*)d_in[1];
    const float* wv  = (const float*)d_in[2];
    const float* wo  = (const float*)d_in[3];
    const float* x   = (const float*)d_in[4];
    const int*   pos = (const int*)d_in[5];
    float* out = (float*)d_out;

    float* dv;
    cudaGetSymbolAddress((void**)&dv, g_v);
    __half *xf, *af, *wf, *qf, *kf, *vtf;
    float2* ropet;
    cudaGetSymbolAddress((void**)&xf,  g_xf);
    cudaGetSymbolAddress((void**)&af,  g_af);
    cudaGetSymbolAddress((void**)&wf,  g_wf);
    cudaGetSymbolAddress((void**)&qf,  g_qf);
    cudaGetSymbolAddress((void**)&kf,  g_kf);
    cudaGetSymbolAddress((void**)&vtf, g_vtf);
    cudaGetSymbolAddress((void**)&ropet, g_rope);

    const size_t WSZ = (size_t)D_MODEL * D_MODEL;
    const int n4x = (int)((size_t)MM * D_MODEL / 4);
    const int n4w = (int)(WSZ / 4);

    rope_table_kernel<<<(SS * HALF) / 256, 256>>>(pos, ropet);
    round_h_kernel<<<(n4x + 255) / 256, 256>>>(x, xf, n4x);
    round4_h_kernel<<<dim3((n4w + 255) / 256, 4), 256>>>(wq, wk, wv, wo, wf, n4w);

    cudaFuncSetAttribute(gemm_fp16_nt<1>,
                         cudaFuncAttributeMaxDynamicSharedMemorySize, 4 * GSTG * 4);
    cudaFuncSetAttribute(gemm_fp16_nt<0>,
                         cudaFuncAttributeMaxDynamicSharedMemorySize, 4 * GSTG * 4);

    // fused QKV: z=0 -> rope-scale-round Q, z=1 -> rope-round K, z=2 -> fp32 V
    gemm_fp16_nt<1><<<dim3(D_MODEL / 128, MM / 128, 3), 256, 4 * GSTG * 4>>>(
        xf, wf, dv, qf, kf, ropet, MM, D_MODEL, D_MODEL);

    vtrans_round_kernel<<<dim3(SS / 64, BB * NUM_HEADS), 256>>>(dv, vtf);

    cudaFuncSetAttribute(attn_tc_kernel,
                         cudaFuncAttributeMaxDynamicSharedMemorySize, 49152);
    attn_tc_kernel<<<dim3(SS / 128, NUM_HEADS, BB), 256, 49152>>>(
        qf, kf, vtf, af);

    // O projection: plain fp32 epilogue, weight slot 3
    gemm_fp16_nt<0><<<dim3(D_MODEL / 128, MM / 128, 1), 256, 4 * GSTG * 4>>>(
        af, wf + 3 * WSZ, out, nullptr, nullptr, ropet, MM, D_MODEL, D_MODEL);
}

// round 16
// speedup vs baseline: 2.8259x; 1.3554x over previous
#include <cuda_runtime.h>
#include <cuda_fp16.h>
#include <math.h>
#include <stdint.h>

#define D_MODEL 1024
#define NUM_HEADS 16
#define DK 64
#define HALF 32
#define BB 4
#define SS 2048
#define MM (BB * SS)           // 8192 tokens
#define LOG2_THETA 13.287712379549449f   // log2(10000)

// ---------------- scratch (device globals: no allocation allowed) ----------
__device__ float g_v[(size_t)MM * D_MODEL];            // V projection (fp32)

__device__ __half g_xf[(size_t)MM * D_MODEL];          // x fp16
__device__ __half g_af[(size_t)MM * D_MODEL];          // attention out fp16
__device__ __half g_wf[4][(size_t)D_MODEL * D_MODEL];  // weights fp16

__device__ __half g_qf[(size_t)MM * D_MODEL];          // Q (roped, pre-scaled) fp16
__device__ __half g_kf[(size_t)MM * D_MODEL];          // K (roped) fp16
__device__ __half g_vtf[(size_t)MM * D_MODEL];         // V^T fp16

__device__ float2 g_rope[(size_t)SS * HALF];           // {cos, sin} table

// ---------------------------------------------------------------------------
__device__ __forceinline__ uint32_t smem_u32(const void* p) {
    return (uint32_t)__cvta_generic_to_shared(p);
}
#define CP_ASYNC16(dst, src) \
    asm volatile("cp.async.cg.shared.global [%0], [%1], 16;\n" :: "r"(dst), "l"(src))
#define CP_COMMIT() asm volatile("cp.async.commit_group;\n" ::: "memory")
#define CP_WAIT2()  asm volatile("cp.async.wait_group 2;\n" ::: "memory")
#define CP_WAIT1()  asm volatile("cp.async.wait_group 1;\n" ::: "memory")
#define CP_WAIT0()  asm volatile("cp.async.wait_group 0;\n" ::: "memory")

#define LDSM_X4(r0, r1, r2, r3, addr) \
    asm volatile("ldmatrix.sync.aligned.m8n8.x4.shared.b16 {%0,%1,%2,%3}, [%4];" \
                 : "=r"(r0), "=r"(r1), "=r"(r2), "=r"(r3) : "r"(addr))

__device__ __forceinline__ void mma_fp16(float c[4], const uint32_t a[4],
                                         const uint32_t b[2]) {
    asm volatile(
        "mma.sync.aligned.m16n8k16.row.col.f32.f16.f16.f32 "
        "{%0,%1,%2,%3}, {%4,%5,%6,%7}, {%8,%9}, {%0,%1,%2,%3};\n"
        : "+f"(c[0]), "+f"(c[1]), "+f"(c[2]), "+f"(c[3])
        : "r"(a[0]), "r"(a[1]), "r"(a[2]), "r"(a[3]), "r"(b[0]), "r"(b[1]));
}

__device__ __forceinline__ uint32_t round2h(float x, float y) {
    __half2 h = __floats2half2_rn(x, y);
    return *(uint32_t*)&h;
}

// ---------------------------------------------------------------------------
// RoPE cos/sin table
// ---------------------------------------------------------------------------
__global__ void __launch_bounds__(256) rope_table_kernel(
    const int* __restrict__ pos, float2* __restrict__ tab)
{
    int idx = blockIdx.x * blockDim.x + threadIdx.x;   // < SS*HALF
    int s = idx >> 5, i = idx & (HALF - 1);
    float p = (float)pos[s];
    float inv_freq = exp2f(-(float)i * (LOG2_THETA / (float)HALF));
    float sn, cs;
    sincosf(p * inv_freq, &sn, &cs);
    tab[idx] = make_float2(cs, sn);
}

// ---------------------------------------------------------------------------
// fp32 -> fp16 round: single tensor, and 4-weight batch
// ---------------------------------------------------------------------------
__global__ void __launch_bounds__(256) round_h_kernel(
    const float* __restrict__ src, __half* __restrict__ dst, int n4)
{
    int i = blockIdx.x * blockDim.x + threadIdx.x;
    if (i >= n4) return;
    float4 v = ((const float4*)src)[i];
    ((uint32_t*)dst)[i * 2 + 0] = round2h(v.x, v.y);
    ((uint32_t*)dst)[i * 2 + 1] = round2h(v.z, v.w);
}

__global__ void __launch_bounds__(256) round4_h_kernel(
    const float* __restrict__ w0, const float* __restrict__ w1,
    const float* __restrict__ w2, const float* __restrict__ w3,
    __half* __restrict__ outB, int n4)
{
    int i = blockIdx.x * blockDim.x + threadIdx.x;
    if (i >= n4) return;
    const int zz = blockIdx.y;
    const float* src = (zz == 0) ? w0 : (zz == 1) ? w1 : (zz == 2) ? w2 : w3;
    __half* dst = outB + (size_t)zz * D_MODEL * D_MODEL;
    float4 v = ((const float4*)src)[i];
    ((uint32_t*)dst)[i * 2 + 0] = round2h(v.x, v.y);
    ((uint32_t*)dst)[i * 2 + 1] = round2h(v.z, v.w);
}

// ---------------------------------------------------------------------------
// fp16 mma.sync GEMM (NT), ldmatrix fragment loads.
// 128x128 tile, BK=32 per stage, 256 threads (8 warps, 2x4), warp tile 64x32.
// Smem per stage: A 128x32h + B 128x32h = 16KB, rows 64B (4 chunks16),
// swizzle phys_chunk = c ^ ((row>>1)&3)  -> conflict-free LDSM + full rows.
// Per warp per k16: 4 LDSM.x4 (A) + 2 LDSM.x4 (B) + 16 MMA.
// FUSED=1 (QKV): z=0 -> rope+scale+round Q; z=1 -> rope+round K; z=2 -> fp32 V.
// FUSED=0 (O-proj): plain fp32 epilogue.
// ---------------------------------------------------------------------------
#define GSTG 4096   // u32 per stage: A 2048 | B 2048

__device__ __forceinline__ void load_stage32(
    const __half* __restrict__ gA, const __half* __restrict__ gB,
    int Kdim, int k0, uint32_t* sb, int tid)
{
    const int m = tid >> 1;            // row 0..127
    const int q = tid & 1;             // which 32B half of the 64B row
    const int s = (m >> 1) & 3;        // swizzle key
    const int p0 = (2 * q) ^ s;
    const int p1 = (2 * q + 1) ^ s;
    const size_t src = (size_t)m * Kdim + k0 + q * 16;
    CP_ASYNC16(smem_u32(sb + m * 16 + p0 * 4),        gA + src);
    CP_ASYNC16(smem_u32(sb + m * 16 + p1 * 4),        gA + src + 8);
    CP_ASYNC16(smem_u32(sb + 2048 + m * 16 + p0 * 4), gB + src);
    CP_ASYNC16(smem_u32(sb + 2048 + m * 16 + p1 * 4), gB + src + 8);
}

template <int FUSED>
__global__ void __launch_bounds__(256) gemm_fp16_nt(
    const __half* __restrict__ A, const __half* __restrict__ WB,
    float* __restrict__ Cf,
    __half* __restrict__ qf, __half* __restrict__ kf,
    const float2* __restrict__ rope,
    int Mdim, int Ndim, int Kdim)
{
    extern __shared__ uint32_t smem4[];   // 4 stages x 4096 u32 = 64KB

    const int tid  = threadIdx.x;
    const int lane = tid & 31;
    const int warp = tid >> 5;
    const int wy   = warp >> 2;
    const int wx   = warp & 3;
    const int row0 = blockIdx.y * 128;
    const int col0 = blockIdx.x * 128;
    const int z    = blockIdx.z;
    const size_t zw = (size_t)z * D_MODEL * D_MODEL;

    const __half* gA = A + (size_t)row0 * Kdim;
    const __half* gB = WB + zw + (size_t)col0 * Kdim;

    // per-thread ldmatrix address components (u32 offsets within a stage)
    // A: frag i (m16): row = wy*64 + i*16 + (lane&15), chunk = ks*2 + (lane>>4)
    int a_rowbase[4], a_sw[4];
    const int a_cl = lane >> 4;                     // 0/1
#pragma unroll
    for (int i = 0; i < 4; ++i) {
        int row = wy * 64 + i * 16 + (lane & 15);
        a_rowbase[i] = row * 16;                    // u32 offset of row start
        a_sw[i] = (row >> 1) & 3;
    }
    // B: x4 jj covers frags 2jj,2jj+1: row = wx*32 + jj*16 + (lane&7) + ((lane&16)>>1)
    int b_rowbase[2], b_sw[2];
    const int b_cl = (lane >> 3) & 1;               // 0/1
#pragma unroll
    for (int jj = 0; jj < 2; ++jj) {
        int row = wx * 32 + jj * 16 + (lane & 7) + ((lane & 16) >> 1);
        b_rowbase[jj] = 2048 * 4 + row * 16;        // bytes later; keep in u32 units: 2048 + row*16? (see below)
        b_sw[jj] = (row >> 1) & 3;
    }

    float c[4][4][4];
#pragma unroll
    for (int i = 0; i < 4; ++i)
#pragma unroll
        for (int j = 0; j < 4; ++j)
#pragma unroll
            for (int r = 0; r < 4; ++r) c[i][j][r] = 0.f;

    const int NT2 = Kdim / 32;            // 32
    load_stage32(gA, gB, Kdim, 0,  smem4,            tid); CP_COMMIT();
    load_stage32(gA, gB, Kdim, 32, smem4 + GSTG,     tid); CP_COMMIT();
    load_stage32(gA, gB, Kdim, 64, smem4 + 2 * GSTG, tid); CP_COMMIT();

    for (int t = 0; t < NT2; ++t) {
        if (t < NT2 - 2)      { CP_WAIT2(); }
        else if (t < NT2 - 1) { CP_WAIT1(); }
        else                  { CP_WAIT0(); }
        __syncthreads();   // data visibility + WAR guard for the issue below

        if (t + 3 < NT2) {
            load_stage32(gA, gB, Kdim, (t + 3) * 32,
                         smem4 + ((t + 3) & 3) * GSTG, tid);
            CP_COMMIT();
        }

        uint32_t* sb = smem4 + (t & 3) * GSTG;
        const uint32_t sbase  = smem_u32(sb);
        const uint32_t sbaseB = smem_u32(sb + 2048);

#pragma unroll
        for (int ks = 0; ks < 2; ++ks) {
            uint32_t a[4][4], b[4][2];
#pragma unroll
            for (int i = 0; i < 4; ++i) {
                int chunk = ((ks * 2 + a_cl) ^ a_sw[i]);
                uint32_t ad = sbase + (uint32_t)(a_rowbase[i] + chunk * 4) * 4u;
                LDSM_X4(a[i][0], a[i][1], a[i][2], a[i][3], ad);
            }
#pragma unroll
            for (int jj = 0; jj < 2; ++jj) {
                int row16 = (b_rowbase[jj] - 2048 * 4);   // u32 offset of row (B region-relative misuse fix)
                int chunk = ((ks * 2 + b_cl) ^ b_sw[jj]);
                uint32_t bd = sbaseB + (uint32_t)(row16 + chunk * 4) * 4u;
                LDSM_X4(b[2 * jj][0], b[2 * jj][1], b[2 * jj + 1][0], b[2 * jj + 1][1], bd);
            }

#pragma unroll
            for (int i = 0; i < 4; ++i)
#pragma unroll
                for (int j = 0; j < 4; ++j)
                    mma_fp16(c[i][j], a[i], b[j]);
        }
    }

    const int r  = lane >> 2;
    const int cc = (lane & 3) * 2;

    if (FUSED && z < 2) {
        __half* of = z ? kf : qf;
        const float sc = z ? 1.0f : 0.125f;   // fold 1/sqrt(dk) into Q (2^-3 exact)
#pragma unroll
        for (int i = 0; i < 4; ++i)
#pragma unroll
            for (int j = 0; j < 4; ++j) {
                const int col = col0 + wx * 32 + j * 8 + cc;       // even
                const int pi  = (col & 63) >> 1;                   // rope pair idx
                const int m0r = row0 + wy * 64 + i * 16 + r;
                const int m1r = m0r + 8;
                float2 t0 = rope[(size_t)(m0r & (SS - 1)) * HALF + pi];
                float2 t1 = rope[(size_t)(m1r & (SS - 1)) * HALF + pi];
                float re0 = (c[i][j][0] * t0.x - c[i][j][1] * t0.y) * sc;
                float ro0 = (c[i][j][0] * t0.y + c[i][j][1] * t0.x) * sc;
                float re1 = (c[i][j][2] * t1.x - c[i][j][3] * t1.y) * sc;
                float ro1 = (c[i][j][2] * t1.y + c[i][j][3] * t1.x) * sc;
                *(uint32_t*)(of + (size_t)m0r * D_MODEL + col) = round2h(re0, ro0);
                *(uint32_t*)(of + (size_t)m1r * D_MODEL + col) = round2h(re1, ro1);
            }
    } else {
#pragma unroll
        for (int i = 0; i < 4; ++i)
#pragma unroll
            for (int j = 0; j < 4; ++j) {
                float* cp = Cf + (size_t)(row0 + wy * 64 + i * 16 + r) * Ndim
                              + col0 + wx * 32 + j * 8 + cc;
                *(float2*)cp = make_float2(c[i][j][0], c[i][j][1]);
                *(float2*)(cp + 8 * (size_t)Ndim) = make_float2(c[i][j][2], c[i][j][3]);
            }
    }
}

// ---------------------------------------------------------------------------
// V transpose + round: fp32 [b*S+t][1024] -> vtf fp16 [(b*16+h)*64+d][S]
// ---------------------------------------------------------------------------
__global__ void __launch_bounds__(256) vtrans_round_kernel(
    const float* __restrict__ v, __half* __restrict__ vtf)
{
    __shared__ float tile[64][65];
    const int tb = blockIdx.x;
    const int bh = blockIdx.y;
    const int b  = bh >> 4, h = bh & 15;
    const int tid = threadIdx.x;

#pragma unroll
    for (int i = 0; i < 4; ++i) {
        int e = tid + i * 256;
        int t = e >> 4;
        int d4 = (e & 15) * 4;
        float4 vv = *(const float4*)(v + (size_t)(b * SS + tb * 64 + t) * D_MODEL
                                       + h * DK + d4);
        tile[d4 + 0][t] = vv.x;
        tile[d4 + 1][t] = vv.y;
        tile[d4 + 2][t] = vv.z;
        tile[d4 + 3][t] = vv.w;
    }
    __syncthreads();

#pragma unroll
    for (int i = 0; i < 8; ++i) {
        int e = tid + i * 256;
        int d = e >> 5;
        int t2 = (e & 31) * 2;
        size_t dst = ((size_t)(bh * 64 + d)) * SS + tb * 64 + t2;
        *(uint32_t*)(vtf + dst) = round2h(tile[d][t2], tile[d][t2 + 1]);
    }
}

// ---------------------------------------------------------------------------
// Tensor-core flash attention (causal), single fp16, 2 CTAs/SM.
// Unchanged from R15 (validated).
// ---------------------------------------------------------------------------
__device__ __forceinline__ void attn_load_tile(
    uint32_t* dsm, int nsb, int tid, int b, int kt, int hoff, size_t vrow0,
    const __half* __restrict__ Kf, const __half* __restrict__ Vtf)
{
#pragma unroll
    for (int i = 0; i < 4; ++i) {
        int c = tid + i * 256;
        if (c < 512) {
            int t = c >> 3, kq = c & 7;
            int wd = ((((t >> 3) * 4 + (kq >> 1)) * 2 + (kq & 1)) << 5) + (t & 7) * 4;
            const __half* src = Kf
                + (size_t)(b * SS + kt * 64 + t) * D_MODEL + hoff + kq * 8;
            CP_ASYNC16(smem_u32(dsm + nsb + wd), src);
        } else {
            int c2 = c - 512;
            int d = c2 >> 3, tq = c2 & 7;
            int wd = ((((d >> 3) * 4 + (tq >> 1)) * 2 + (tq & 1)) << 5) + (d & 7) * 4;
            const __half* src = Vtf + vrow0 + (size_t)d * SS + kt * 64 + tq * 8;
            CP_ASYNC16(smem_u32(dsm + nsb + 2048 + wd), src);
        }
    }
}

__global__ void __launch_bounds__(256, 2) attn_tc_kernel(
    const __half* __restrict__ Qf, const __half* __restrict__ Kf,
    const __half* __restrict__ Vtf, __half* __restrict__ Af)
{
    extern __shared__ uint32_t dsm[];   // 12288 u32 = 48KB

    const int qi  = (gridDim.x - 1) - blockIdx.x;   // big work first (LPT)
    const int h   = blockIdx.y;
    const int b   = blockIdx.z;
    const int tid = threadIdx.x;
    const int lane = tid & 31;
    const int w    = tid >> 5;

    const int tok0 = b * SS + qi * 128;
    const int hoff = h * DK;
    const size_t vrow0 = (size_t)((b * 16 + h) * 64) * SS;
    const int kt_last = qi * 2 + 1;

#pragma unroll
    for (int i = 0; i < 4; ++i) {
        int c = tid + i * 256;
        int m = c >> 3, kq = c & 7;
        int wd = ((((m >> 4) * 4 + (kq >> 1)) * 4 + ((m >> 3) & 1) + 2 * (kq & 1)) << 5)
                 + (m & 7) * 4;
        const __half* src = Qf + (size_t)(tok0 + m) * D_MODEL + hoff + kq * 8;
        CP_ASYNC16(smem_u32(dsm + 8192 + wd), src);
    }
    attn_load_tile(dsm, 0, tid, b, 0, hoff, vrow0, Kf, Vtf);
    CP_COMMIT();
    CP_WAIT0();
    __syncthreads();

    uint32_t qf[4][4];
#pragma unroll
    for (int ks = 0; ks < 4; ++ks)
#pragma unroll
        for (int r = 0; r < 4; ++r) {
            int wd = (((w * 4 + ks) * 4 + r) << 5) + lane;
            qf[ks][r] = dsm[8192 + wd];
        }
    __syncthreads();

    float acc[8][4];
#pragma unroll
    for (int j = 0; j < 8; ++j)
#pragma unroll
        for (int r = 0; r < 4; ++r) acc[j][r] = 0.f;
    float m0 = -1e30f, m1 = -1e30f, l0 = 0.f, l1 = 0.f;

    const int q0w = qi * 128 + w * 16;

    for (int kt = 0; kt <= kt_last; ++kt) {
        const int sb = (kt & 1) * 4096;
        CP_WAIT0();
        __syncthreads();

        if (kt < kt_last) {
            attn_load_tile(dsm, ((kt + 1) & 1) * 4096, tid, b, kt + 1,
                           hoff, vrow0, Kf, Vtf);
            CP_COMMIT();
        }

        if (kt * 64 <= q0w + 15) {
            const uint32_t* sK = dsm + sb;
            const uint32_t* sV = dsm + sb + 2048;

            float s[8][4];
#pragma unroll
            for (int j = 0; j < 8; ++j)
#pragma unroll
                for (int r = 0; r < 4; ++r) s[j][r] = 0.f;

#pragma unroll
            for (int ks = 0; ks < 4; ++ks)
#pragma unroll
                for (int jn = 0; jn < 8; ++jn) {
                    int base = ((jn * 4 + ks) << 6) + lane;
                    uint32_t bf[2] = {sK[base], sK[base + 32]};
                    mma_fp16(s[jn], qf[ks], bf);
                }

            if (kt * 64 + 63 > q0w) {
                const int row0g = q0w + (lane >> 2);
                const int colbg = kt * 64 + 2 * (lane & 3);
#pragma unroll
                for (int jn = 0; jn < 8; ++jn) {
                    int c0 = colbg + jn * 8;
                    if (c0 > row0g)     s[jn][0] = -1e30f;
                    if (c0 + 1 > row0g) s[jn][1] = -1e30f;
                    if (c0 > row0g + 8)     s[jn][2] = -1e30f;
                    if (c0 + 1 > row0g + 8) s[jn][3] = -1e30f;
                }
            }

            float mx0 = -1e30f, mx1 = -1e30f;
#pragma unroll
            for (int j = 0; j < 8; ++j) {
                mx0 = fmaxf(mx0, fmaxf(s[j][0], s[j][1]));
                mx1 = fmaxf(mx1, fmaxf(s[j][2], s[j][3]));
            }
            mx0 = fmaxf(mx0, __shfl_xor_sync(0xffffffffu, mx0, 1));
            mx0 = fmaxf(mx0, __shfl_xor_sync(0xffffffffu, mx0, 2));
            mx1 = fmaxf(mx1, __shfl_xor_sync(0xffffffffu, mx1, 1));
            mx1 = fmaxf(mx1, __shfl_xor_sync(0xffffffffu, mx1, 2));

            float mn0 = fmaxf(m0, mx0), mn1 = fmaxf(m1, mx1);
            float al0 = __expf(m0 - mn0), al1 = __expf(m1 - mn1);
            m0 = mn0; m1 = mn1;

            float sum0 = 0.f, sum1 = 0.f;
#pragma unroll
            for (int j = 0; j < 8; ++j) {
                s[j][0] = __expf(s[j][0] - mn0);
                s[j][1] = __expf(s[j][1] - mn0);
                s[j][2] = __expf(s[j][2] - mn1);
                s[j][3] = __expf(s[j][3] - mn1);
                sum0 += s[j][0] + s[j][1];
                sum1 += s[j][2] + s[j][3];
            }
            sum0 += __shfl_xor_sync(0xffffffffu, sum0, 1);
            sum0 += __shfl_xor_sync(0xffffffffu, sum0, 2);
            sum1 += __shfl_xor_sync(0xffffffffu, sum1, 1);
            sum1 += __shfl_xor_sync(0xffffffffu, sum1, 2);
            l0 = l0 * al0 + sum0;
            l1 = l1 * al1 + sum1;

#pragma unroll
            for (int j = 0; j < 8; ++j) {
                acc[j][0] *= al0; acc[j][1] *= al0;
                acc[j][2] *= al1; acc[j][3] *= al1;
            }

#pragma unroll
            for (int kk = 0; kk < 4; ++kk) {
                uint32_t pf4[4];
                pf4[0] = round2h(s[2 * kk][0],     s[2 * kk][1]);
                pf4[1] = round2h(s[2 * kk][2],     s[2 * kk][3]);
                pf4[2] = round2h(s[2 * kk + 1][0], s[2 * kk + 1][1]);
                pf4[3] = round2h(s[2 * kk + 1][2], s[2 * kk + 1][3]);
#pragma unroll
                for (int jd = 0; jd < 8; ++jd) {
                    int base = ((jd * 4 + kk) << 6) + lane;
                    uint32_t vf[2] = {sV[base], sV[base + 32]};
                    mma_fp16(acc[jd], pf4, vf);
                }
            }
        }
    }

    const float inv0 = 1.f / l0, inv1 = 1.f / l1;
    const int r  = lane >> 2;
    const int cc = 2 * (lane & 3);
    const size_t r0 = (size_t)(tok0 + w * 16 + r) * D_MODEL + hoff;
    const size_t r1 = r0 + 8 * (size_t)D_MODEL;
#pragma unroll
    for (int jd = 0; jd < 8; ++jd) {
        *(uint32_t*)(Af + r0 + jd * 8 + cc) = round2h(acc[jd][0] * inv0, acc[jd][1] * inv0);
        *(uint32_t*)(Af + r1 + jd * 8 + cc) = round2h(acc[jd][2] * inv1, acc[jd][3] * inv1);
    }
}

// ---------------------------------------------------------------------------
extern "C" void kernel_launch(void* const* d_in, const int* in_sizes, int n_in,
                              void* d_out, int out_size)
{
    const float* wq  = (const float*)d_in[0];
    const float* wk  = (const float*)d_in[1];
    const float* wv  = (const float*)d_in[2];
    const float* wo  = (const float*)d_in[3];
    const float* x   = (const float*)d_in[4];
    const int*   pos = (const int*)d_in[5];
    float* out = (float*)d_out;

    float* dv;
    cudaGetSymbolAddress((void**)&dv, g_v);
    __half *xf, *af, *wf, *qf, *kf, *vtf;
    float2* ropet;
    cudaGetSymbolAddress((void**)&xf,  g_xf);
    cudaGetSymbolAddress((void**)&af,  g_af);
    cudaGetSymbolAddress((void**)&wf,  g_wf);
    cudaGetSymbolAddress((void**)&qf,  g_qf);
    cudaGetSymbolAddress((void**)&kf,  g_kf);
    cudaGetSymbolAddress((void**)&vtf, g_vtf);
    cudaGetSymbolAddress((void**)&ropet, g_rope);

    const size_t WSZ = (size_t)D_MODEL * D_MODEL;
    const int n4x = (int)((size_t)MM * D_MODEL / 4);
    const int n4w = (int)(WSZ / 4);

    rope_table_kernel<<<(SS * HALF) / 256, 256>>>(pos, ropet);
    round_h_kernel<<<(n4x + 255) / 256, 256>>>(x, xf, n4x);
    round4_h_kernel<<<dim3((n4w + 255) / 256, 4), 256>>>(wq, wk, wv, wo, wf, n4w);

    cudaFuncSetAttribute(gemm_fp16_nt<1>,
                         cudaFuncAttributeMaxDynamicSharedMemorySize, 4 * GSTG * 4);
    cudaFuncSetAttribute(gemm_fp16_nt<0>,
                         cudaFuncAttributeMaxDynamicSharedMemorySize, 4 * GSTG * 4);

    // fused QKV: z=0 -> rope-scale-round Q, z=1 -> rope-round K, z=2 -> fp32 V
    gemm_fp16_nt<1><<<dim3(D_MODEL / 128, MM / 128, 3), 256, 4 * GSTG * 4>>>(
        xf, wf, dv, qf, kf, ropet, MM, D_MODEL, D_MODEL);

    vtrans_round_kernel<<<dim3(SS / 64, BB * NUM_HEADS), 256>>>(dv, vtf);

    cudaFuncSetAttribute(attn_tc_kernel,
                         cudaFuncAttributeMaxDynamicSharedMemorySize, 49152);
    attn_tc_kernel<<<dim3(SS / 128, NUM_HEADS, BB), 256, 49152>>>(
        qf, kf, vtf, af);

    // O projection: plain fp32 epilogue, weight slot 3
    gemm_fp16_nt<0><<<dim3(D_MODEL / 128, MM / 128, 1), 256, 4 * GSTG * 4>>>(
        af, wf + 3 * WSZ, out, nullptr, nullptr, ropet, MM, D_MODEL, D_MODEL);
}

// round 17
// speedup vs baseline: 3.2573x; 1.1527x over previous
#include <cuda_runtime.h>
#include <cuda_fp16.h>
#include <math.h>
#include <stdint.h>

#define D_MODEL 1024
#define NUM_HEADS 16
#define DK 64
#define HALF 32
#define BB 4
#define SS 2048
#define MM (BB * SS)           // 8192 tokens
#define LOG2_THETA 13.287712379549449f   // log2(10000)

// ---------------- scratch (device globals: no allocation allowed) ----------
__device__ float g_v[(size_t)MM * D_MODEL];            // V projection (fp32)

__device__ __half g_xf[(size_t)MM * D_MODEL];          // x fp16
__device__ __half g_af[(size_t)MM * D_MODEL];          // attention out fp16
__device__ __half g_wf[4][(size_t)D_MODEL * D_MODEL];  // weights fp16

__device__ __half g_qf[(size_t)MM * D_MODEL];          // Q (roped, pre-scaled) fp16
__device__ __half g_kf[(size_t)MM * D_MODEL];          // K (roped) fp16
__device__ __half g_vtf[(size_t)MM * D_MODEL];         // V^T fp16

__device__ float2 g_rope[(size_t)SS * HALF];           // {cos, sin} table

// ---------------------------------------------------------------------------
__device__ __forceinline__ uint32_t smem_u32(const void* p) {
    return (uint32_t)__cvta_generic_to_shared(p);
}
#define CP_ASYNC16(dst, src) \
    asm volatile("cp.async.cg.shared.global [%0], [%1], 16;\n" :: "r"(dst), "l"(src))
#define CP_COMMIT() asm volatile("cp.async.commit_group;\n" ::: "memory")
#define CP_WAIT2()  asm volatile("cp.async.wait_group 2;\n" ::: "memory")
#define CP_WAIT1()  asm volatile("cp.async.wait_group 1;\n" ::: "memory")
#define CP_WAIT0()  asm volatile("cp.async.wait_group 0;\n" ::: "memory")

#define LDSM_X4(r0, r1, r2, r3, addr) \
    asm volatile("ldmatrix.sync.aligned.m8n8.x4.shared.b16 {%0,%1,%2,%3}, [%4];" \
                 : "=r"(r0), "=r"(r1), "=r"(r2), "=r"(r3) : "r"(addr))

__device__ __forceinline__ void mma_fp16(float c[4], const uint32_t a[4],
                                         const uint32_t b[2]) {
    asm volatile(
        "mma.sync.aligned.m16n8k16.row.col.f32.f16.f16.f32 "
        "{%0,%1,%2,%3}, {%4,%5,%6,%7}, {%8,%9}, {%0,%1,%2,%3};\n"
        : "+f"(c[0]), "+f"(c[1]), "+f"(c[2]), "+f"(c[3])
        : "r"(a[0]), "r"(a[1]), "r"(a[2]), "r"(a[3]), "r"(b[0]), "r"(b[1]));
}

__device__ __forceinline__ uint32_t round2h(float x, float y) {
    __half2 h = __floats2half2_rn(x, y);
    return *(uint32_t*)&h;
}

// ---------------------------------------------------------------------------
// RoPE cos/sin table
// ---------------------------------------------------------------------------
__global__ void __launch_bounds__(256) rope_table_kernel(
    const int* __restrict__ pos, float2* __restrict__ tab)
{
    int idx = blockIdx.x * blockDim.x + threadIdx.x;   // < SS*HALF
    int s = idx >> 5, i = idx & (HALF - 1);
    float p = (float)pos[s];
    float inv_freq = exp2f(-(float)i * (LOG2_THETA / (float)HALF));
    float sn, cs;
    sincosf(p * inv_freq, &sn, &cs);
    tab[idx] = make_float2(cs, sn);
}

// ---------------------------------------------------------------------------
// fp32 -> fp16 round: single tensor, and 4-weight batch
// ---------------------------------------------------------------------------
__global__ void __launch_bounds__(256) round_h_kernel(
    const float* __restrict__ src, __half* __restrict__ dst, int n4)
{
    int i = blockIdx.x * blockDim.x + threadIdx.x;
    if (i >= n4) return;
    float4 v = ((const float4*)src)[i];
    ((uint32_t*)dst)[i * 2 + 0] = round2h(v.x, v.y);
    ((uint32_t*)dst)[i * 2 + 1] = round2h(v.z, v.w);
}

__global__ void __launch_bounds__(256) round4_h_kernel(
    const float* __restrict__ w0, const float* __restrict__ w1,
    const float* __restrict__ w2, const float* __restrict__ w3,
    __half* __restrict__ outB, int n4)
{
    int i = blockIdx.x * blockDim.x + threadIdx.x;
    if (i >= n4) return;
    const int zz = blockIdx.y;
    const float* src = (zz == 0) ? w0 : (zz == 1) ? w1 : (zz == 2) ? w2 : w3;
    __half* dst = outB + (size_t)zz * D_MODEL * D_MODEL;
    float4 v = ((const float4*)src)[i];
    ((uint32_t*)dst)[i * 2 + 0] = round2h(v.x, v.y);
    ((uint32_t*)dst)[i * 2 + 1] = round2h(v.z, v.w);
}

// ---------------------------------------------------------------------------
// fp16 mma.sync GEMM (NT), ldmatrix fragment loads — unchanged (R16 WIN).
// ---------------------------------------------------------------------------
#define GSTG 4096   // u32 per stage: A 2048 | B 2048

__device__ __forceinline__ void load_stage32(
    const __half* __restrict__ gA, const __half* __restrict__ gB,
    int Kdim, int k0, uint32_t* sb, int tid)
{
    const int m = tid >> 1;            // row 0..127
    const int q = tid & 1;             // which 32B half of the 64B row
    const int s = (m >> 1) & 3;        // swizzle key
    const int p0 = (2 * q) ^ s;
    const int p1 = (2 * q + 1) ^ s;
    const size_t src = (size_t)m * Kdim + k0 + q * 16;
    CP_ASYNC16(smem_u32(sb + m * 16 + p0 * 4),        gA + src);
    CP_ASYNC16(smem_u32(sb + m * 16 + p1 * 4),        gA + src + 8);
    CP_ASYNC16(smem_u32(sb + 2048 + m * 16 + p0 * 4), gB + src);
    CP_ASYNC16(smem_u32(sb + 2048 + m * 16 + p1 * 4), gB + src + 8);
}

template <int FUSED>
__global__ void __launch_bounds__(256) gemm_fp16_nt(
    const __half* __restrict__ A, const __half* __restrict__ WB,
    float* __restrict__ Cf,
    __half* __restrict__ qf, __half* __restrict__ kf,
    const float2* __restrict__ rope,
    int Mdim, int Ndim, int Kdim)
{
    extern __shared__ uint32_t smem4[];   // 4 stages x 4096 u32 = 64KB

    const int tid  = threadIdx.x;
    const int lane = tid & 31;
    const int warp = tid >> 5;
    const int wy   = warp >> 2;
    const int wx   = warp & 3;
    const int row0 = blockIdx.y * 128;
    const int col0 = blockIdx.x * 128;
    const int z    = blockIdx.z;
    const size_t zw = (size_t)z * D_MODEL * D_MODEL;

    const __half* gA = A + (size_t)row0 * Kdim;
    const __half* gB = WB + zw + (size_t)col0 * Kdim;

    int a_rowbase[4], a_sw[4];
    const int a_cl = lane >> 4;
#pragma unroll
    for (int i = 0; i < 4; ++i) {
        int row = wy * 64 + i * 16 + (lane & 15);
        a_rowbase[i] = row * 16;
        a_sw[i] = (row >> 1) & 3;
    }
    int b_rowbase[2], b_sw[2];
    const int b_cl = (lane >> 3) & 1;
#pragma unroll
    for (int jj = 0; jj < 2; ++jj) {
        int row = wx * 32 + jj * 16 + (lane & 7) + ((lane & 16) >> 1);
        b_rowbase[jj] = row * 16;
        b_sw[jj] = (row >> 1) & 3;
    }

    float c[4][4][4];
#pragma unroll
    for (int i = 0; i < 4; ++i)
#pragma unroll
        for (int j = 0; j < 4; ++j)
#pragma unroll
            for (int r = 0; r < 4; ++r) c[i][j][r] = 0.f;

    const int NT2 = Kdim / 32;            // 32
    load_stage32(gA, gB, Kdim, 0,  smem4,            tid); CP_COMMIT();
    load_stage32(gA, gB, Kdim, 32, smem4 + GSTG,     tid); CP_COMMIT();
    load_stage32(gA, gB, Kdim, 64, smem4 + 2 * GSTG, tid); CP_COMMIT();

    for (int t = 0; t < NT2; ++t) {
        if (t < NT2 - 2)      { CP_WAIT2(); }
        else if (t < NT2 - 1) { CP_WAIT1(); }
        else                  { CP_WAIT0(); }
        __syncthreads();

        if (t + 3 < NT2) {
            load_stage32(gA, gB, Kdim, (t + 3) * 32,
                         smem4 + ((t + 3) & 3) * GSTG, tid);
            CP_COMMIT();
        }

        uint32_t* sb = smem4 + (t & 3) * GSTG;
        const uint32_t sbase  = smem_u32(sb);
        const uint32_t sbaseB = smem_u32(sb + 2048);

#pragma unroll
        for (int ks = 0; ks < 2; ++ks) {
            uint32_t a[4][4], b[4][2];
#pragma unroll
            for (int i = 0; i < 4; ++i) {
                int chunk = ((ks * 2 + a_cl) ^ a_sw[i]);
                uint32_t ad = sbase + (uint32_t)(a_rowbase[i] + chunk * 4) * 4u;
                LDSM_X4(a[i][0], a[i][1], a[i][2], a[i][3], ad);
            }
#pragma unroll
            for (int jj = 0; jj < 2; ++jj) {
                int chunk = ((ks * 2 + b_cl) ^ b_sw[jj]);
                uint32_t bd = sbaseB + (uint32_t)(b_rowbase[jj] + chunk * 4) * 4u;
                LDSM_X4(b[2 * jj][0], b[2 * jj][1], b[2 * jj + 1][0], b[2 * jj + 1][1], bd);
            }

#pragma unroll
            for (int i = 0; i < 4; ++i)
#pragma unroll
                for (int j = 0; j < 4; ++j)
                    mma_fp16(c[i][j], a[i], b[j]);
        }
    }

    const int r  = lane >> 2;
    const int cc = (lane & 3) * 2;

    if (FUSED && z < 2) {
        __half* of = z ? kf : qf;
        const float sc = z ? 1.0f : 0.125f;
#pragma unroll
        for (int i = 0; i < 4; ++i)
#pragma unroll
            for (int j = 0; j < 4; ++j) {
                const int col = col0 + wx * 32 + j * 8 + cc;
                const int pi  = (col & 63) >> 1;
                const int m0r = row0 + wy * 64 + i * 16 + r;
                const int m1r = m0r + 8;
                float2 t0 = rope[(size_t)(m0r & (SS - 1)) * HALF + pi];
                float2 t1 = rope[(size_t)(m1r & (SS - 1)) * HALF + pi];
                float re0 = (c[i][j][0] * t0.x - c[i][j][1] * t0.y) * sc;
                float ro0 = (c[i][j][0] * t0.y + c[i][j][1] * t0.x) * sc;
                float re1 = (c[i][j][2] * t1.x - c[i][j][3] * t1.y) * sc;
                float ro1 = (c[i][j][2] * t1.y + c[i][j][3] * t1.x) * sc;
                *(uint32_t*)(of + (size_t)m0r * D_MODEL + col) = round2h(re0, ro0);
                *(uint32_t*)(of + (size_t)m1r * D_MODEL + col) = round2h(re1, ro1);
            }
    } else {
#pragma unroll
        for (int i = 0; i < 4; ++i)
#pragma unroll
            for (int j = 0; j < 4; ++j) {
                float* cp = Cf + (size_t)(row0 + wy * 64 + i * 16 + r) * Ndim
                              + col0 + wx * 32 + j * 8 + cc;
                *(float2*)cp = make_float2(c[i][j][0], c[i][j][1]);
                *(float2*)(cp + 8 * (size_t)Ndim) = make_float2(c[i][j][2], c[i][j][3]);
            }
    }
}

// ---------------------------------------------------------------------------
// V transpose + round: fp32 [b*S+t][1024] -> vtf fp16 [(b*16+h)*64+d][S]
// ---------------------------------------------------------------------------
__global__ void __launch_bounds__(256) vtrans_round_kernel(
    const float* __restrict__ v, __half* __restrict__ vtf)
{
    __shared__ float tile[64][65];
    const int tb = blockIdx.x;
    const int bh = blockIdx.y;
    const int b  = bh >> 4, h = bh & 15;
    const int tid = threadIdx.x;

#pragma unroll
    for (int i = 0; i < 4; ++i) {
        int e = tid + i * 256;
        int t = e >> 4;
        int d4 = (e & 15) * 4;
        float4 vv = *(const float4*)(v + (size_t)(b * SS + tb * 64 + t) * D_MODEL
                                       + h * DK + d4);
        tile[d4 + 0][t] = vv.x;
        tile[d4 + 1][t] = vv.y;
        tile[d4 + 2][t] = vv.z;
        tile[d4 + 3][t] = vv.w;
    }
    __syncthreads();

#pragma unroll
    for (int i = 0; i < 8; ++i) {
        int e = tid + i * 256;
        int d = e >> 5;
        int t2 = (e & 31) * 2;
        size_t dst = ((size_t)(bh * 64 + d)) * SS + tb * 64 + t2;
        *(uint32_t*)(vtf + dst) = round2h(tile[d][t2], tile[d][t2 + 1]);
    }
}

// ---------------------------------------------------------------------------
// Tensor-core flash attention (causal), fp16, 2 CTAs/SM, LDSM fragment loads.
// Smem rows: 64 fp16 = 128B = 8 chunks16; swizzle phys = c ^ (row & 7).
// K tile 8KB | V tile 8KB per stage (x2), Q 16KB at offset 8192. Total 48KB.
// Per k-tile per warp: 16 LDSM.x4 (K) + 16 LDSM.x4 (V) + 64 MMA.
// ---------------------------------------------------------------------------
__device__ __forceinline__ void attn_load_tile(
    uint32_t* dsm, int nsb, int tid, int b, int kt, int hoff, size_t vrow0,
    const __half* __restrict__ Kf, const __half* __restrict__ Vtf)
{
#pragma unroll
    for (int i = 0; i < 4; ++i) {
        int c = tid + i * 256;
        if (c < 512) {                       // K: row = t (0..63), 8 chunks
            int row = c >> 3, ch = c & 7;
            int phys = ch ^ (row & 7);
            const __half* src = Kf
                + (size_t)(b * SS + kt * 64 + row) * D_MODEL + hoff + ch * 8;
            CP_ASYNC16(smem_u32(dsm + nsb + row * 32 + phys * 4), src);
        } else {                             // V: row = d (0..63)
            int c2 = c - 512;
            int row = c2 >> 3, ch = c2 & 7;
            int phys = ch ^ (row & 7);
            const __half* src = Vtf + vrow0 + (size_t)row * SS + kt * 64 + ch * 8;
            CP_ASYNC16(smem_u32(dsm + nsb + 2048 + row * 32 + phys * 4), src);
        }
    }
}

__global__ void __launch_bounds__(256, 2) attn_tc_kernel(
    const __half* __restrict__ Qf, const __half* __restrict__ Kf,
    const __half* __restrict__ Vtf, __half* __restrict__ Af)
{
    extern __shared__ uint32_t dsm[];   // 12288 u32 = 48KB

    const int qi  = (gridDim.x - 1) - blockIdx.x;   // big work first (LPT)
    const int h   = blockIdx.y;
    const int b   = blockIdx.z;
    const int tid = threadIdx.x;
    const int lane = tid & 31;
    const int w    = tid >> 5;

    const int tok0 = b * SS + qi * 128;
    const int hoff = h * DK;
    const size_t vrow0 = (size_t)((b * 16 + h) * 64) * SS;
    const int kt_last = qi * 2 + 1;

    // prologue: Q rows (128 x 8 chunks, swizzled) into 8192.., tile0 stage0
#pragma unroll
    for (int i = 0; i < 4; ++i) {
        int c = tid + i * 256;                // 0..1023
        int row = c >> 3, ch = c & 7;
        int phys = ch ^ (row & 7);
        const __half* src = Qf + (size_t)(tok0 + row) * D_MODEL + hoff + ch * 8;
        CP_ASYNC16(smem_u32(dsm + 8192 + row * 32 + phys * 4), src);
    }
    attn_load_tile(dsm, 0, tid, b, 0, hoff, vrow0, Kf, Vtf);
    CP_COMMIT();
    CP_WAIT0();
    __syncthreads();

    // Q fragments via ldmatrix (A-form): row = w*16+(lane&15), chunk 2ks+(lane>>4)
    uint32_t qf[4][4];
    {
        const int qrow = w * 16 + (lane & 15);
        const int qsw  = qrow & 7;
        const int qcl  = lane >> 4;
#pragma unroll
        for (int ks = 0; ks < 4; ++ks) {
            int chunk = (2 * ks + qcl) ^ qsw;
            uint32_t ad = smem_u32(dsm + 8192 + qrow * 32 + chunk * 4);
            LDSM_X4(qf[ks][0], qf[ks][1], qf[ks][2], qf[ks][3], ad);
        }
    }
    __syncthreads();

    // B-form per-thread row components (shared by K and V fragment loads)
    int f_rowbase[4], f_sw[4];
    const int f_cl = (lane >> 3) & 1;
#pragma unroll
    for (int jj = 0; jj < 4; ++jj) {
        int row = jj * 16 + (lane & 7) + ((lane & 16) >> 1);
        f_rowbase[jj] = row * 32;
        f_sw[jj] = row & 7;
    }

    float acc[8][4];
#pragma unroll
    for (int j = 0; j < 8; ++j)
#pragma unroll
        for (int r = 0; r < 4; ++r) acc[j][r] = 0.f;
    float m0 = -1e30f, m1 = -1e30f, l0 = 0.f, l1 = 0.f;

    const int q0w = qi * 128 + w * 16;

    for (int kt = 0; kt <= kt_last; ++kt) {
        const int sb = (kt & 1) * 4096;
        CP_WAIT0();
        __syncthreads();

        if (kt < kt_last) {
            attn_load_tile(dsm, ((kt + 1) & 1) * 4096, tid, b, kt + 1,
                           hoff, vrow0, Kf, Vtf);
            CP_COMMIT();
        }

        if (kt * 64 <= q0w + 15) {
            const uint32_t sKb = smem_u32(dsm + sb);
            const uint32_t sVb = smem_u32(dsm + sb + 2048);

            float s[8][4];
#pragma unroll
            for (int j = 0; j < 8; ++j)
#pragma unroll
                for (int r = 0; r < 4; ++r) s[j][r] = 0.f;

            // ---- S = Q K^T ----
#pragma unroll
            for (int ks = 0; ks < 4; ++ks) {
                uint32_t bK[8][2];
#pragma unroll
                for (int jj = 0; jj < 4; ++jj) {
                    int chunk = (2 * ks + f_cl) ^ f_sw[jj];
                    uint32_t ad = sKb + (uint32_t)(f_rowbase[jj] + chunk * 4) * 4u;
                    LDSM_X4(bK[2 * jj][0], bK[2 * jj][1],
                            bK[2 * jj + 1][0], bK[2 * jj + 1][1], ad);
                }
#pragma unroll
                for (int jn = 0; jn < 8; ++jn)
                    mma_fp16(s[jn], qf[ks], bK[jn]);
            }

            if (kt * 64 + 63 > q0w) {
                const int row0g = q0w + (lane >> 2);
                const int colbg = kt * 64 + 2 * (lane & 3);
#pragma unroll
                for (int jn = 0; jn < 8; ++jn) {
                    int c0 = colbg + jn * 8;
                    if (c0 > row0g)     s[jn][0] = -1e30f;
                    if (c0 + 1 > row0g) s[jn][1] = -1e30f;
                    if (c0 > row0g + 8)     s[jn][2] = -1e30f;
                    if (c0 + 1 > row0g + 8) s[jn][3] = -1e30f;
                }
            }

            float mx0 = -1e30f, mx1 = -1e30f;
#pragma unroll
            for (int j = 0; j < 8; ++j) {
                mx0 = fmaxf(mx0, fmaxf(s[j][0], s[j][1]));
                mx1 = fmaxf(mx1, fmaxf(s[j][2], s[j][3]));
            }
            mx0 = fmaxf(mx0, __shfl_xor_sync(0xffffffffu, mx0, 1));
            mx0 = fmaxf(mx0, __shfl_xor_sync(0xffffffffu, mx0, 2));
            mx1 = fmaxf(mx1, __shfl_xor_sync(0xffffffffu, mx1, 1));
            mx1 = fmaxf(mx1, __shfl_xor_sync(0xffffffffu, mx1, 2));

            float mn0 = fmaxf(m0, mx0), mn1 = fmaxf(m1, mx1);
            float al0 = __expf(m0 - mn0), al1 = __expf(m1 - mn1);
            m0 = mn0; m1 = mn1;

            float sum0 = 0.f, sum1 = 0.f;
#pragma unroll
            for (int j = 0; j < 8; ++j) {
                s[j][0] = __expf(s[j][0] - mn0);
                s[j][1] = __expf(s[j][1] - mn0);
                s[j][2] = __expf(s[j][2] - mn1);
                s[j][3] = __expf(s[j][3] - mn1);
                sum0 += s[j][0] + s[j][1];
                sum1 += s[j][2] + s[j][3];
            }
            sum0 += __shfl_xor_sync(0xffffffffu, sum0, 1);
            sum0 += __shfl_xor_sync(0xffffffffu, sum0, 2);
            sum1 += __shfl_xor_sync(0xffffffffu, sum1, 1);
            sum1 += __shfl_xor_sync(0xffffffffu, sum1, 2);
            l0 = l0 * al0 + sum0;
            l1 = l1 * al1 + sum1;

#pragma unroll
            for (int j = 0; j < 8; ++j) {
                acc[j][0] *= al0; acc[j][1] *= al0;
                acc[j][2] *= al1; acc[j][3] *= al1;
            }

            // ---- O += P V ----
#pragma unroll
            for (int kk = 0; kk < 4; ++kk) {
                uint32_t pf4[4];
                pf4[0] = round2h(s[2 * kk][0],     s[2 * kk][1]);
                pf4[1] = round2h(s[2 * kk][2],     s[2 * kk][3]);
                pf4[2] = round2h(s[2 * kk + 1][0], s[2 * kk + 1][1]);
                pf4[3] = round2h(s[2 * kk + 1][2], s[2 * kk + 1][3]);
                uint32_t bV[8][2];
#pragma unroll
                for (int jj = 0; jj < 4; ++jj) {
                    int chunk = (2 * kk + f_cl) ^ f_sw[jj];
                    uint32_t ad = sVb + (uint32_t)(f_rowbase[jj] + chunk * 4) * 4u;
                    LDSM_X4(bV[2 * jj][0], bV[2 * jj][1],
                            bV[2 * jj + 1][0], bV[2 * jj + 1][1], ad);
                }
#pragma unroll
                for (int jd = 0; jd < 8; ++jd)
                    mma_fp16(acc[jd], pf4, bV[jd]);
            }
        }
    }

    const float inv0 = 1.f / l0, inv1 = 1.f / l1;
    const int r  = lane >> 2;
    const int cc = 2 * (lane & 3);
    const size_t r0 = (size_t)(tok0 + w * 16 + r) * D_MODEL + hoff;
    const size_t r1 = r0 + 8 * (size_t)D_MODEL;
#pragma unroll
    for (int jd = 0; jd < 8; ++jd) {
        *(uint32_t*)(Af + r0 + jd * 8 + cc) = round2h(acc[jd][0] * inv0, acc[jd][1] * inv0);
        *(uint32_t*)(Af + r1 + jd * 8 + cc) = round2h(acc[jd][2] * inv1, acc[jd][3] * inv1);
    }
}

// ---------------------------------------------------------------------------
extern "C" void kernel_launch(void* const* d_in, const int* in_sizes, int n_in,
                              void* d_out, int out_size)
{
    const float* wq  = (const float*)d_in[0];
    const float* wk  = (const float*)d_in[1];
    const float* wv  = (const float*)d_in[2];
    const float* wo  = (const float*)d_in[3];
    const float* x   = (const float*)d_in[4];
    const int*   pos = (const int*)d_in[5];
    float* out = (float*)d_out;

    float* dv;
    cudaGetSymbolAddress((void**)&dv, g_v);
    __half *xf, *af, *wf, *qf, *kf, *vtf;
    float2* ropet;
    cudaGetSymbolAddress((void**)&xf,  g_xf);
    cudaGetSymbolAddress((void**)&af,  g_af);
    cudaGetSymbolAddress((void**)&wf,  g_wf);
    cudaGetSymbolAddress((void**)&qf,  g_qf);
    cudaGetSymbolAddress((void**)&kf,  g_kf);
    cudaGetSymbolAddress((void**)&vtf, g_vtf);
    cudaGetSymbolAddress((void**)&ropet, g_rope);

    const size_t WSZ = (size_t)D_MODEL * D_MODEL;
    const int n4x = (int)((size_t)MM * D_MODEL / 4);
    const int n4w = (int)(WSZ / 4);

    rope_table_kernel<<<(SS * HALF) / 256, 256>>>(pos, ropet);
    round_h_kernel<<<(n4x + 255) / 256, 256>>>(x, xf, n4x);
    round4_h_kernel<<<dim3((n4w + 255) / 256, 4), 256>>>(wq, wk, wv, wo, wf, n4w);

    cudaFuncSetAttribute(gemm_fp16_nt<1>,
                         cudaFuncAttributeMaxDynamicSharedMemorySize, 4 * GSTG * 4);
    cudaFuncSetAttribute(gemm_fp16_nt<0>,
                         cudaFuncAttributeMaxDynamicSharedMemorySize, 4 * GSTG * 4);

    // fused QKV: z=0 -> rope-scale-round Q, z=1 -> rope-round K, z=2 -> fp32 V
    gemm_fp16_nt<1><<<dim3(D_MODEL / 128, MM / 128, 3), 256, 4 * GSTG * 4>>>(
        xf, wf, dv, qf, kf, ropet, MM, D_MODEL, D_MODEL);

    vtrans_round_kernel<<<dim3(SS / 64, BB * NUM_HEADS), 256>>>(dv, vtf);

    cudaFuncSetAttribute(attn_tc_kernel,
                         cudaFuncAttributeMaxDynamicSharedMemorySize, 49152);
    attn_tc_kernel<<<dim3(SS / 128, NUM_HEADS, BB), 256, 49152>>>(
        qf, kf, vtf, af);

    // O projection: plain fp32 epilogue, weight slot 3
    gemm_fp16_nt<0><<<dim3(D_MODEL / 128, MM / 128, 1), 256, 4 * GSTG * 4>>>(
        af, wf + 3 * WSZ, out, nullptr, nullptr, ropet, MM, D_MODEL, D_MODEL);
}